// round 1
// baseline (speedup 1.0000x reference)
#include <cuda_runtime.h>
#include <math.h>

#define N_ITER 10

static __device__ float d_p[5];                     // separable 1D psf
static __device__ float d_T[192 * 192 * 192];       // conv_xy(x) temp
static __device__ float d_E[96 * 192 * 192];        // conv_xy(residual) planes
static __device__ float d_A[192 * 192 * 192];       // ping
static __device__ float d_B[192 * 192 * 192];       // pong

// ---------------------------------------------------------------------------
// Recover separable 1D kernel: p[i] = sum_{j,k} psf[i,j,k]
// ---------------------------------------------------------------------------
__global__ void init_p_kernel(const float* __restrict__ psf) {
    int i = threadIdx.x;
    if (i < 5) {
        float s = 0.f;
        for (int j = 0; j < 25; ++j) s += psf[i * 25 + j];
        d_p[i] = s;
    }
}

// ---------------------------------------------------------------------------
// K1: T = conv_y(conv_x(x)) on every z-plane. Tile 32x8, halo 2.
// ---------------------------------------------------------------------------
__global__ __launch_bounds__(256) void conv_xy_kernel(
    const float* __restrict__ x, float* __restrict__ T, int D, int H, int W) {
    __shared__ float sIn[12][40];
    __shared__ float sMid[12][32];

    const int z = blockIdx.z;
    const int x0 = blockIdx.x * 32, y0 = blockIdx.y * 8;
    const int tx = threadIdx.x, ty = threadIdx.y;
    const float* plane = x + (size_t)z * H * W;

    for (int yy = ty; yy < 12; yy += 8) {
        int gy = y0 + yy - 2;
        for (int xx = tx; xx < 36; xx += 32) {
            int gx = x0 + xx - 2;
            float v = 0.f;
            if ((unsigned)gy < (unsigned)H && (unsigned)gx < (unsigned)W)
                v = plane[gy * W + gx];
            sIn[yy][xx] = v;
        }
    }
    __syncthreads();

    const float p0 = d_p[0], p1 = d_p[1], p2 = d_p[2], p3 = d_p[3], p4 = d_p[4];

    for (int yy = ty; yy < 12; yy += 8) {
        float v = p0 * sIn[yy][tx]     + p1 * sIn[yy][tx + 1] + p2 * sIn[yy][tx + 2]
                + p3 * sIn[yy][tx + 3] + p4 * sIn[yy][tx + 4];
        sMid[yy][tx] = v;
    }
    __syncthreads();

    int gy = y0 + ty, gx = x0 + tx;
    if (gy < H && gx < W) {
        float v = p0 * sMid[ty][tx]     + p1 * sMid[ty + 1][tx] + p2 * sMid[ty + 2][tx]
                + p3 * sMid[ty + 3][tx] + p4 * sMid[ty + 4][tx];
        T[(size_t)z * H * W + gy * W + gx] = v;
    }
}

// ---------------------------------------------------------------------------
// K2: for slice plane i at z = i*stride:
//     F = sum_dz p[dz]*T[z+dz-2] - slices[i];  E[i] = conv_y(conv_x(F))
// ---------------------------------------------------------------------------
__global__ __launch_bounds__(256) void make_E_kernel(
    const float* __restrict__ T, const float* __restrict__ slices,
    float* __restrict__ E, const int* __restrict__ stridep,
    int D, int H, int W) {
    __shared__ float sF[12][40];
    __shared__ float sMid[12][32];

    const int i = blockIdx.z;
    const int zi = i * (*stridep);
    const int x0 = blockIdx.x * 32, y0 = blockIdx.y * 8;
    const int tx = threadIdx.x, ty = threadIdx.y;
    const size_t HW = (size_t)H * W;

    const float p0 = d_p[0], p1 = d_p[1], p2 = d_p[2], p3 = d_p[3], p4 = d_p[4];
    float pz[5] = {p0, p1, p2, p3, p4};

    for (int yy = ty; yy < 12; yy += 8) {
        int gy = y0 + yy - 2;
        for (int xx = tx; xx < 36; xx += 32) {
            int gx = x0 + xx - 2;
            float v = 0.f;
            if ((unsigned)gy < (unsigned)H && (unsigned)gx < (unsigned)W) {
                float acc = 0.f;
                #pragma unroll
                for (int dz = 0; dz < 5; ++dz) {
                    int zz = zi + dz - 2;
                    if ((unsigned)zz < (unsigned)D)
                        acc += pz[dz] * T[(size_t)zz * HW + gy * W + gx];
                }
                v = acc - slices[(size_t)i * HW + gy * W + gx];
            }
            sF[yy][xx] = v;
        }
    }
    __syncthreads();

    for (int yy = ty; yy < 12; yy += 8) {
        float v = p0 * sF[yy][tx]     + p1 * sF[yy][tx + 1] + p2 * sF[yy][tx + 2]
                + p3 * sF[yy][tx + 3] + p4 * sF[yy][tx + 4];
        sMid[yy][tx] = v;
    }
    __syncthreads();

    int gy = y0 + ty, gx = x0 + tx;
    if (gy < H && gx < W) {
        float v = p0 * sMid[ty][tx]     + p1 * sMid[ty + 1][tx] + p2 * sMid[ty + 2][tx]
                + p3 * sMid[ty + 3][tx] + p4 * sMid[ty + 4][tx];
        E[(size_t)i * HW + gy * W + gx] = v;
    }
}

// ---------------------------------------------------------------------------
// K3: x_out = x - ALPHA*( At_z(E) + BETA*dR(x) ), optional ReLU.
// Tile 32x8x2, halo 1 for the 26-neighbor regularizer.
// ---------------------------------------------------------------------------
__global__ __launch_bounds__(512) void update_kernel(
    const float* __restrict__ xin, const float* __restrict__ E,
    float* __restrict__ xout, const int* __restrict__ stridep,
    int n_slices, int D, int H, int W, int do_relu) {
    __shared__ float s[4][10][36];

    const int x0 = blockIdx.x * 32, y0 = blockIdx.y * 8, z0 = blockIdx.z * 2;
    const int tx = threadIdx.x, ty = threadIdx.y, tz = threadIdx.z;
    const size_t HW = (size_t)H * W;

    // cooperative halo load: (4 z) x (10 y) x (34 x)
    int tid = (tz * 8 + ty) * 32 + tx;
    for (int idx = tid; idx < 4 * 10 * 34; idx += 512) {
        int lz = idx / 340;
        int r = idx % 340;
        int ly = r / 34;
        int lx = r % 34;
        int gz = z0 - 1 + lz, gy = y0 - 1 + ly, gx = x0 - 1 + lx;
        float v = 0.f;
        if ((unsigned)gz < (unsigned)D && (unsigned)gy < (unsigned)H &&
            (unsigned)gx < (unsigned)W)
            v = xin[(size_t)gz * HW + gy * W + gx];
        s[lz][ly][lx] = v;
    }
    __syncthreads();

    const int z = z0 + tz, y = y0 + ty, x = x0 + tx;
    if (z >= D || y >= H || x >= W) return;

    const float v0 = s[tz + 1][ty + 1][tx + 1];

    // data term: g[z] = sum_dz p[dz] * E[(z+dz-2)/stride] when aligned
    const int stride = *stridep;
    float gd = 0.f;
    const float p0 = d_p[0], p1 = d_p[1], p2 = d_p[2], p3 = d_p[3], p4 = d_p[4];
    float pz[5] = {p0, p1, p2, p3, p4};
    if (stride == 2) {
        #pragma unroll
        for (int dz = 0; dz < 5; ++dz) {
            int zz = z + dz - 2;
            if ((unsigned)zz < (unsigned)D && !(zz & 1)) {
                int pi = zz >> 1;
                if (pi < n_slices)
                    gd += pz[dz] * E[(size_t)pi * HW + y * W + x];
            }
        }
    } else {
        #pragma unroll
        for (int dz = 0; dz < 5; ++dz) {
            int zz = z + dz - 2;
            if ((unsigned)zz < (unsigned)D && (zz % stride) == 0) {
                int pi = zz / stride;
                if (pi < n_slices)
                    gd += pz[dz] * E[(size_t)pi * HW + y * W + x];
            }
        }
    }

    // regularizer (interior only)
    float greg = 0.f;
    if (z > 0 && z < D - 1 && y > 0 && y < H - 1 && x > 0 && x < W - 1) {
        #pragma unroll
        for (int ddz = -1; ddz <= 1; ++ddz)
            #pragma unroll
            for (int ddy = -1; ddy <= 1; ++ddy)
                #pragma unroll
                for (int ddx = -1; ddx <= 1; ++ddx) {
                    if (ddx == 0 && ddy == 0 && ddz == 0) continue;
                    const int d2 = ddx * ddx + ddy * ddy + ddz * ddz;
                    const float w = (float)(1.0 / ((double)d2 * (0.1 * 0.1)));
                    float v1 = s[tz + 1 + ddz][ty + 1 + ddy][tx + 1 + ddx];
                    float dv = v0 - v1;
                    float t = dv * w;
                    greg += t * rsqrtf(fmaf(dv, t, 1.0f));
                }
    }

    const float ALPHA = 0.5f;
    const float BETA = (float)(0.02 * 0.1 * 0.1);
    float xn = v0 - ALPHA * (gd + BETA * greg);
    if (do_relu) xn = fmaxf(xn, 0.f);
    xout[(size_t)z * HW + y * W + x] = xn;
}

// ---------------------------------------------------------------------------
extern "C" void kernel_launch(void* const* d_in, const int* in_sizes, int n_in,
                              void* d_out, int out_size) {
    const float* slices = (const float*)d_in[1];
    const float* volume = (const float*)d_in[2];
    const float* psf    = (const float*)d_in[3];
    const int* stridep  = (const int*)d_in[4];

    int D = (int)lround(cbrt((double)out_size));   // 192
    int H = D, W = D;
    int n_slices = in_sizes[1] / (H * W);

    float *pT, *pE, *pA, *pB;
    cudaGetSymbolAddress((void**)&pT, d_T);
    cudaGetSymbolAddress((void**)&pE, d_E);
    cudaGetSymbolAddress((void**)&pA, d_A);
    cudaGetSymbolAddress((void**)&pB, d_B);

    init_p_kernel<<<1, 32>>>(psf);

    dim3 blk2(32, 8, 1);
    dim3 grid_xy((W + 31) / 32, (H + 7) / 8, D);
    dim3 grid_E((W + 31) / 32, (H + 7) / 8, n_slices);
    dim3 blk3(32, 8, 2);
    dim3 grid_up((W + 31) / 32, (H + 7) / 8, (D + 1) / 2);

    for (int it = 0; it < N_ITER; ++it) {
        const float* xin = (it == 0) ? volume : ((it & 1) ? pA : pB);
        float* xout = (it == N_ITER - 1) ? (float*)d_out
                                         : ((it & 1) ? pB : pA);
        int do_relu = (it == N_ITER - 1) ? 1 : 0;

        conv_xy_kernel<<<grid_xy, blk2>>>(xin, pT, D, H, W);
        make_E_kernel<<<grid_E, blk2>>>(pT, slices, pE, stridep, D, H, W);
        update_kernel<<<grid_up, blk3>>>(xin, pE, xout, stridep, n_slices,
                                         D, H, W, do_relu);
    }
}

// round 3
// speedup vs baseline: 1.2529x; 1.2529x over previous
#include <cuda_runtime.h>
#include <math.h>

#define N_ITER 10

static __device__ float d_p[5];                     // separable 1D psf
static __device__ float d_E[96 * 192 * 192];        // conv_xy(residual) planes
static __device__ float d_A[192 * 192 * 192];       // ping
static __device__ float d_B[192 * 192 * 192];       // pong

// ---------------------------------------------------------------------------
// Recover separable 1D kernel: p[i] = sum_{j,k} psf[i,j,k]
// ---------------------------------------------------------------------------
__global__ void init_p_kernel(const float* __restrict__ psf) {
    int i = threadIdx.x;
    if (i < 5) {
        float s = 0.f;
        for (int j = 0; j < 25; ++j) s += psf[i * 25 + j];
        d_p[i] = s;
    }
}

// ---------------------------------------------------------------------------
// Fused forward+residual+adjoint-xy kernel:
// For slice i at zi = i*stride:
//   Z  = conv_z(x) at plane zi         (on 16x40 halo tile)
//   F  = conv_y(conv_x(Z)) - slices[i] (on 12x36 halo tile, 0 outside image)
//   E  = conv_y(conv_x(F))             (8x32 output tile)
// ---------------------------------------------------------------------------
__global__ __launch_bounds__(256) void fused_E_kernel(
    const float* __restrict__ x, const float* __restrict__ slices,
    float* __restrict__ E, const int* __restrict__ stridep,
    int D, int H, int W, int n_slices) {
    __shared__ float sZ[16][42];
    __shared__ float sA[16][38];
    __shared__ float sF[12][38];
    __shared__ float sB[12][36];

    const int i = blockIdx.z;
    const int zi = i * (*stridep);
    const int x0 = blockIdx.x * 32, y0 = blockIdx.y * 8;
    const int tx = threadIdx.x, ty = threadIdx.y;
    const int tid = ty * 32 + tx;
    const size_t HW = (size_t)H * W;

    const float p0 = d_p[0], p1 = d_p[1], p2 = d_p[2], p3 = d_p[3], p4 = d_p[4];

    // step 1: z-combine into sZ (16 rows x 40 cols halo tile)
    for (int idx = tid; idx < 16 * 40; idx += 256) {
        int r = idx / 40, c = idx % 40;
        int gy = y0 - 4 + r, gx = x0 - 4 + c;
        float acc = 0.f;
        if ((unsigned)gy < (unsigned)H && (unsigned)gx < (unsigned)W) {
            const float* col = x + (size_t)gy * W + gx;
            int z0 = zi - 2;
            if (z0 >= 0 && z0 < D)         acc = fmaf(p0, col[(size_t)z0 * HW], acc);
            if (z0 + 1 >= 0 && z0 + 1 < D) acc = fmaf(p1, col[(size_t)(z0 + 1) * HW], acc);
            if (z0 + 2 >= 0 && z0 + 2 < D) acc = fmaf(p2, col[(size_t)(z0 + 2) * HW], acc);
            if (z0 + 3 >= 0 && z0 + 3 < D) acc = fmaf(p3, col[(size_t)(z0 + 3) * HW], acc);
            if (z0 + 4 >= 0 && z0 + 4 < D) acc = fmaf(p4, col[(size_t)(z0 + 4) * HW], acc);
        }
        sZ[r][c] = acc;
    }
    __syncthreads();

    // step 2: x-conv into sA (16 x 36)
    for (int idx = tid; idx < 16 * 36; idx += 256) {
        int r = idx / 36, c = idx % 36;
        float v = p0 * sZ[r][c]     + p1 * sZ[r][c + 1] + p2 * sZ[r][c + 2]
                + p3 * sZ[r][c + 3] + p4 * sZ[r][c + 4];
        sA[r][c] = v;
    }
    __syncthreads();

    // step 3: y-conv + subtract slice into sF (12 x 36); 0 outside image
    for (int idx = tid; idx < 12 * 36; idx += 256) {
        int r = idx / 36, c = idx % 36;
        int gy = y0 - 2 + r, gx = x0 - 2 + c;
        float v = 0.f;
        if ((unsigned)gy < (unsigned)H && (unsigned)gx < (unsigned)W) {
            v = p0 * sA[r][c]     + p1 * sA[r + 1][c] + p2 * sA[r + 2][c]
              + p3 * sA[r + 3][c] + p4 * sA[r + 4][c];
            v -= slices[(size_t)i * HW + gy * W + gx];
        }
        sF[r][c] = v;
    }
    __syncthreads();

    // step 4: x-conv into sB (12 x 32)
    for (int idx = tid; idx < 12 * 32; idx += 256) {
        int r = idx >> 5, c = idx & 31;
        float v = p0 * sF[r][c]     + p1 * sF[r][c + 1] + p2 * sF[r][c + 2]
                + p3 * sF[r][c + 3] + p4 * sF[r][c + 4];
        sB[r][c] = v;
    }
    __syncthreads();

    // step 5: y-conv, store E (8 x 32)
    int gy = y0 + ty, gx = x0 + tx;
    if (gy < H && gx < W) {
        float v = p0 * sB[ty][tx]     + p1 * sB[ty + 1][tx] + p2 * sB[ty + 2][tx]
                + p3 * sB[ty + 3][tx] + p4 * sB[ty + 4][tx];
        E[(size_t)i * HW + gy * W + gx] = v;
    }
}

// ---------------------------------------------------------------------------
// z-rolling update: x_out = x - ALPHA*( At_z(E) + BETA*dR(x) ), optional ReLU.
// Block 32x8, walks CHUNK z-planes; 3-plane smem ring; 3x3 neighborhoods
// rolled in registers (only the new plane's 9 values hit smem each step).
// ---------------------------------------------------------------------------
#define UPD_CHUNK 24

__global__ __launch_bounds__(256, 4) void update_roll_kernel(
    const float* __restrict__ xin, const float* __restrict__ E,
    float* __restrict__ xout, const int* __restrict__ stridep,
    int n_slices, int D, int H, int W, int do_relu) {
    __shared__ float s[3][10][36];

    const int x0 = blockIdx.x * 32, y0 = blockIdx.y * 8;
    const int zb = blockIdx.z * UPD_CHUNK;
    const int tx = threadIdx.x, ty = threadIdx.y;
    const int tid = ty * 32 + tx;
    const size_t HW = (size_t)H * W;
    const int y = y0 + ty, x = x0 + tx;
    const int stride = *stridep;

    const float p0 = d_p[0], p1 = d_p[1], p2 = d_p[2], p3 = d_p[3], p4 = d_p[4];
    const float pz[5] = {p0, p1, p2, p3, p4};

    // regularizer weights by squared distance (match reference f32 rounding)
    const float w1 = (float)(1.0 / (1.0 * 0.1 * 0.1));
    const float w2 = (float)(1.0 / (2.0 * 0.1 * 0.1));
    const float w3 = (float)(1.0 / (3.0 * 0.1 * 0.1));

    auto loadPlane = [&](int z, int sl) {
        for (int idx = tid; idx < 340; idx += 256) {
            int ly = idx / 34, lx = idx % 34;
            int gy = y0 - 1 + ly, gx = x0 - 1 + lx;
            float v = 0.f;
            if ((unsigned)z < (unsigned)D && (unsigned)gy < (unsigned)H &&
                (unsigned)gx < (unsigned)W)
                v = xin[(size_t)z * HW + gy * W + gx];
            s[sl][ly][lx] = v;
        }
    };

    const int sl_m1 = ((zb - 1) % 3 + 3) % 3;
    const int sl_0  = zb % 3;
    loadPlane(zb - 1, sl_m1);
    loadPlane(zb, sl_0);
    __syncthreads();

    float A[9], B[9];
    #pragma unroll
    for (int dy = 0; dy < 3; ++dy)
        #pragma unroll
        for (int dx = 0; dx < 3; ++dx) {
            A[dy * 3 + dx] = s[sl_m1][ty + dy][tx + dx];
            B[dy * 3 + dx] = s[sl_0][ty + dy][tx + dx];
        }

    const bool iy = (y > 0 && y < H - 1);
    const bool ix = (x > 0 && x < W - 1);
    const size_t eo = (size_t)y * W + x;
    const float ALPHA = 0.5f;
    const float BETA = (float)(0.02 * 0.1 * 0.1);

    int zend = zb + UPD_CHUNK;
    if (zend > D) zend = D;

    for (int z = zb; z < zend; ++z) {
        const int sl = (z + 1) % 3;
        loadPlane(z + 1, sl);
        __syncthreads();

        float C[9];
        #pragma unroll
        for (int dy = 0; dy < 3; ++dy)
            #pragma unroll
            for (int dx = 0; dx < 3; ++dx)
                C[dy * 3 + dx] = s[sl][ty + dy][tx + dx];

        const float v0 = B[4];

        // ---- data term: conv_z^T of E planes ----
        float gd = 0.f;
        if (stride == 2) {
            int h = z >> 1;
            if ((z & 1) == 0) {
                if (z >= 2)                          gd = fmaf(pz[0], E[(size_t)(h - 1) * HW + eo], gd);
                if (h < n_slices)                    gd = fmaf(pz[2], E[(size_t)h * HW + eo], gd);
                if (z + 2 < D && h + 1 < n_slices)   gd = fmaf(pz[4], E[(size_t)(h + 1) * HW + eo], gd);
            } else {
                if (h < n_slices)                    gd = fmaf(pz[1], E[(size_t)h * HW + eo], gd);
                if (z + 1 < D && h + 1 < n_slices)   gd = fmaf(pz[3], E[(size_t)(h + 1) * HW + eo], gd);
            }
        } else {
            #pragma unroll
            for (int dz = 0; dz < 5; ++dz) {
                int zz = z + dz - 2;
                if ((unsigned)zz < (unsigned)D && (zz % stride) == 0) {
                    int pi = zz / stride;
                    if (pi < n_slices) gd = fmaf(pz[dz], E[(size_t)pi * HW + eo], gd);
                }
            }
        }

        // ---- regularizer (interior only) ----
        float greg = 0.f;
        if (iy && ix && z > 0 && z < D - 1) {
            #pragma unroll
            for (int j = 0; j < 9; ++j) {
                int dy = j / 3 - 1, dx = j % 3 - 1;
                int d2a = dy * dy + dx * dx + 1;       // A/C planes (dz=+-1)
                float wa = (d2a == 1) ? w1 : ((d2a == 2) ? w2 : w3);
                {
                    float dv = v0 - A[j];
                    float t = dv * wa;
                    greg += t * rsqrtf(fmaf(dv, t, 1.0f));
                }
                {
                    float dv = v0 - C[j];
                    float t = dv * wa;
                    greg += t * rsqrtf(fmaf(dv, t, 1.0f));
                }
                if (j != 4) {
                    int d2b = dy * dy + dx * dx;        // B plane (dz=0)
                    float wb = (d2b == 1) ? w1 : ((d2b == 2) ? w2 : w3);
                    float dv = v0 - B[j];
                    float t = dv * wb;
                    greg += t * rsqrtf(fmaf(dv, t, 1.0f));
                }
            }
        }

        float xn = v0 - ALPHA * (gd + BETA * greg);
        if (do_relu) xn = fmaxf(xn, 0.f);
        xout[(size_t)z * HW + eo] = xn;

        #pragma unroll
        for (int j = 0; j < 9; ++j) { A[j] = B[j]; B[j] = C[j]; }
    }
}

// ---------------------------------------------------------------------------
extern "C" void kernel_launch(void* const* d_in, const int* in_sizes, int n_in,
                              void* d_out, int out_size) {
    const float* slices = (const float*)d_in[1];
    const float* volume = (const float*)d_in[2];
    const float* psf    = (const float*)d_in[3];
    const int* stridep  = (const int*)d_in[4];

    int D = (int)lround(cbrt((double)out_size));   // 192
    int H = D, W = D;
    int n_slices = in_sizes[1] / (H * W);

    float *pE, *pA, *pB;
    cudaGetSymbolAddress((void**)&pE, d_E);
    cudaGetSymbolAddress((void**)&pA, d_A);
    cudaGetSymbolAddress((void**)&pB, d_B);

    init_p_kernel<<<1, 32>>>(psf);

    dim3 blk(32, 8, 1);
    dim3 grid_E((W + 31) / 32, (H + 7) / 8, n_slices);
    dim3 grid_up((W + 31) / 32, (H + 7) / 8, (D + UPD_CHUNK - 1) / UPD_CHUNK);

    for (int it = 0; it < N_ITER; ++it) {
        const float* xin = (it == 0) ? volume : ((it & 1) ? pA : pB);
        float* xout = (it == N_ITER - 1) ? (float*)d_out
                                         : ((it & 1) ? pB : pA);
        int do_relu = (it == N_ITER - 1) ? 1 : 0;

        fused_E_kernel<<<grid_E, blk>>>(xin, slices, pE, stridep,
                                        D, H, W, n_slices);
        update_roll_kernel<<<grid_up, blk>>>(xin, pE, xout, stridep, n_slices,
                                             D, H, W, do_relu);
    }
}

// round 4
// speedup vs baseline: 1.7523x; 1.3986x over previous
#include <cuda_runtime.h>
#include <math.h>

#define N_ITER 10

static __device__ float d_p[5];                     // separable 1D psf
static __device__ float d_E[96 * 192 * 192];        // conv_xy(residual) planes
static __device__ float d_A[192 * 192 * 192];       // ping
static __device__ float d_B[192 * 192 * 192];       // pong

// ---------------------------------------------------------------------------
__global__ void init_p_kernel(const float* __restrict__ psf) {
    int i = threadIdx.x;
    if (i < 5) {
        float s = 0.f;
        for (int j = 0; j < 25; ++j) s += psf[i * 25 + j];
        d_p[i] = s;
    }
}

// ---------------------------------------------------------------------------
// Fused forward+residual+adjoint-xy kernel, 32x32 output tile, divide-free.
// For slice i at zi = i*stride:
//   sZ = conv_z(x) at plane zi          (40x40 halo tile)
//   sA = conv_x(sZ)                     (40x36)
//   sF = conv_y(sA) - slices[i]         (36x36, 0 outside image)
//   sB = conv_x(sF)                     (36x32)
//   E  = conv_y(sB)                     (32x32 output)
// Block (32,8): rows strided by 8, cols = tx (+32 for low lanes).
// ---------------------------------------------------------------------------
__global__ __launch_bounds__(256) void fused_E_kernel(
    const float* __restrict__ x, const float* __restrict__ slices,
    float* __restrict__ E, const int* __restrict__ stridep,
    int D, int H, int W, int n_slices) {
    __shared__ float sZ[40][44];
    __shared__ float sA[40][36];
    __shared__ float sF[36][36];
    __shared__ float sB[36][33];

    const int i = blockIdx.z;
    const int zi = i * (*stridep);
    const int x0 = blockIdx.x * 32, y0 = blockIdx.y * 32;
    const int tx = threadIdx.x, ty = threadIdx.y;
    const size_t HW = (size_t)H * W;

    const float p0 = d_p[0], p1 = d_p[1], p2 = d_p[2], p3 = d_p[3], p4 = d_p[4];

    // ---- step 1: z-combine into sZ (40 rows x 40 cols), halo 4 ----
    {
        const int z0 = zi - 2;
        const bool zok0 = (z0 >= 0);
        const bool zok1 = (z0 + 1 >= 0);          // z0+1 >= 0 <=> zi >= 1
        const bool zok3 = (z0 + 3 < D);
        const bool zok4 = (z0 + 4 < D);
        #pragma unroll
        for (int k = 0; k < 5; ++k) {
            const int r = ty + 8 * k;
            const int gy = y0 - 4 + r;
            const bool okY = (unsigned)gy < (unsigned)H;
            // col batch 0: c = tx
            {
                const int gx = x0 - 4 + tx;
                float acc = 0.f;
                if (okY && (unsigned)gx < (unsigned)W) {
                    const float* col = x + (size_t)gy * W + gx + (size_t)z0 * HW;
                    if (zok0) acc = fmaf(p0, col[0], acc);
                    if (zok1) acc = fmaf(p1, col[HW], acc);
                    acc = fmaf(p2, col[2 * HW], acc);
                    if (zok3) acc = fmaf(p3, col[3 * HW], acc);
                    if (zok4) acc = fmaf(p4, col[4 * HW], acc);
                }
                sZ[r][tx] = acc;
            }
            // col batch 1: c = 32 + tx (tx < 8)
            if (tx < 8) {
                const int c = 32 + tx;
                const int gx = x0 - 4 + c;
                float acc = 0.f;
                if (okY && (unsigned)gx < (unsigned)W) {
                    const float* col = x + (size_t)gy * W + gx + (size_t)z0 * HW;
                    if (zok0) acc = fmaf(p0, col[0], acc);
                    if (zok1) acc = fmaf(p1, col[HW], acc);
                    acc = fmaf(p2, col[2 * HW], acc);
                    if (zok3) acc = fmaf(p3, col[3 * HW], acc);
                    if (zok4) acc = fmaf(p4, col[4 * HW], acc);
                }
                sZ[r][c] = acc;
            }
        }
    }
    __syncthreads();

    // ---- step 2: x-conv into sA (40 rows x 36 cols) ----
    #pragma unroll
    for (int k = 0; k < 5; ++k) {
        const int r = ty + 8 * k;
        {
            const int c = tx;
            sA[r][c] = p0 * sZ[r][c]     + p1 * sZ[r][c + 1] + p2 * sZ[r][c + 2]
                     + p3 * sZ[r][c + 3] + p4 * sZ[r][c + 4];
        }
        if (tx < 4) {
            const int c = 32 + tx;
            sA[r][c] = p0 * sZ[r][c]     + p1 * sZ[r][c + 1] + p2 * sZ[r][c + 2]
                     + p3 * sZ[r][c + 3] + p4 * sZ[r][c + 4];
        }
    }
    __syncthreads();

    // ---- step 3: y-conv + subtract slice into sF (36 x 36); 0 outside ----
    {
        const float* sl = slices + (size_t)i * HW;
        #pragma unroll
        for (int k = 0; k < 5; ++k) {
            const int r = (k < 4) ? (ty + 8 * k) : (32 + ty);
            if (k == 4 && ty >= 4) break;
            const int gy = y0 - 2 + r;
            const bool okY = (unsigned)gy < (unsigned)H;
            {
                const int c = tx;
                const int gx = x0 - 2 + c;
                float v = 0.f;
                if (okY && (unsigned)gx < (unsigned)W) {
                    v = p0 * sA[r][c]     + p1 * sA[r + 1][c] + p2 * sA[r + 2][c]
                      + p3 * sA[r + 3][c] + p4 * sA[r + 4][c];
                    v -= sl[(size_t)gy * W + gx];
                }
                sF[r][c] = v;
            }
            if (tx < 4) {
                const int c = 32 + tx;
                const int gx = x0 - 2 + c;
                float v = 0.f;
                if (okY && (unsigned)gx < (unsigned)W) {
                    v = p0 * sA[r][c]     + p1 * sA[r + 1][c] + p2 * sA[r + 2][c]
                      + p3 * sA[r + 3][c] + p4 * sA[r + 4][c];
                    v -= sl[(size_t)gy * W + gx];
                }
                sF[r][c] = v;
            }
        }
    }
    __syncthreads();

    // ---- step 4: x-conv into sB (36 x 32) ----
    #pragma unroll
    for (int k = 0; k < 5; ++k) {
        const int r = (k < 4) ? (ty + 8 * k) : (32 + ty);
        if (k == 4 && ty >= 4) break;
        sB[r][tx] = p0 * sF[r][tx]     + p1 * sF[r][tx + 1] + p2 * sF[r][tx + 2]
                  + p3 * sF[r][tx + 3] + p4 * sF[r][tx + 4];
    }
    __syncthreads();

    // ---- step 5: y-conv, store E (32 x 32) ----
    {
        float* Ei = E + (size_t)i * HW;
        #pragma unroll
        for (int k = 0; k < 4; ++k) {
            const int r = ty + 8 * k;
            const int gy = y0 + r, gx = x0 + tx;
            float v = p0 * sB[r][tx]     + p1 * sB[r + 1][tx] + p2 * sB[r + 2][tx]
                    + p3 * sB[r + 3][tx] + p4 * sB[r + 4][tx];
            Ei[(size_t)gy * W + gx] = v;
        }
    }
}

// ---------------------------------------------------------------------------
// z-rolling update: x_out = x - ALPHA*( At_z(E) + BETA*dR(x) ), optional ReLU.
// Block 32x8, walks CHUNK z-planes; 3-plane smem ring; 3x3 neighborhoods
// rolled in registers. All cooperative-load indexing hoisted out of z loop.
// ---------------------------------------------------------------------------
#define UPD_CHUNK 24

__global__ __launch_bounds__(256, 4) void update_roll_kernel(
    const float* __restrict__ xin, const float* __restrict__ E,
    float* __restrict__ xout, const int* __restrict__ stridep,
    int n_slices, int D, int H, int W, int do_relu) {
    __shared__ float s[3][10][36];

    const int x0 = blockIdx.x * 32, y0 = blockIdx.y * 8;
    const int zb = blockIdx.z * UPD_CHUNK;
    const int tx = threadIdx.x, ty = threadIdx.y;
    const int tid = ty * 32 + tx;
    const size_t HW = (size_t)H * W;
    const int y = y0 + ty, x = x0 + tx;
    const int stride = *stridep;

    const float p0 = d_p[0], p1 = d_p[1], p2 = d_p[2], p3 = d_p[3], p4 = d_p[4];
    const float pz[5] = {p0, p1, p2, p3, p4};

    const float w1 = (float)(1.0 / (1.0 * 0.1 * 0.1));
    const float w2 = (float)(1.0 / (2.0 * 0.1 * 0.1));
    const float w3 = (float)(1.0 / (3.0 * 0.1 * 0.1));

    // ---- hoisted cooperative-load geometry (340 = 10*34 slots) ----
    const int ly0 = tid / 34, lx0 = tid % 34;         // once per block
    const int gy0 = y0 - 1 + ly0, gx0 = x0 - 1 + lx0;
    const bool ok0 = (unsigned)gy0 < (unsigned)H && (unsigned)gx0 < (unsigned)W;
    const size_t off0 = ok0 ? ((size_t)gy0 * W + gx0) : 0;

    const int i1 = tid + 256;
    const bool has1 = (i1 < 340);
    const int ly1 = i1 / 34, lx1 = i1 % 34;
    const int gy1 = y0 - 1 + ly1, gx1 = x0 - 1 + lx1;
    const bool ok1 = has1 && (unsigned)gy1 < (unsigned)H && (unsigned)gx1 < (unsigned)W;
    const size_t off1 = ok1 ? ((size_t)gy1 * W + gx1) : 0;

    auto loadPlane = [&](int z, int sl) {
        const bool zok = (unsigned)z < (unsigned)D;
        const size_t zo = (size_t)(zok ? z : 0) * HW;
        s[sl][ly0][lx0] = (zok && ok0) ? xin[zo + off0] : 0.f;
        if (has1) s[sl][ly1][lx1] = (zok && ok1) ? xin[zo + off1] : 0.f;
    };

    const int sl_m1 = ((zb - 1) % 3 + 3) % 3;
    const int sl_0  = zb % 3;
    loadPlane(zb - 1, sl_m1);
    loadPlane(zb, sl_0);
    __syncthreads();

    float A[9], B[9];
    #pragma unroll
    for (int dy = 0; dy < 3; ++dy)
        #pragma unroll
        for (int dx = 0; dx < 3; ++dx) {
            A[dy * 3 + dx] = s[sl_m1][ty + dy][tx + dx];
            B[dy * 3 + dx] = s[sl_0][ty + dy][tx + dx];
        }

    const bool interior_xy = (y > 0 && y < H - 1 && x > 0 && x < W - 1);
    const size_t eo = (size_t)y * W + x;
    const float* Ecol = E + eo;
    float* outcol = xout + eo;
    const float* incol_chk = nullptr; (void)incol_chk;
    const float ALPHA = 0.5f;
    const float BETA = (float)(0.02 * 0.1 * 0.1);

    int zend = zb + UPD_CHUNK;
    if (zend > D) zend = D;

    for (int z = zb; z < zend; ++z) {
        const int sl = (z + 1) % 3;
        loadPlane(z + 1, sl);
        __syncthreads();

        float C[9];
        #pragma unroll
        for (int dy = 0; dy < 3; ++dy)
            #pragma unroll
            for (int dx = 0; dx < 3; ++dx)
                C[dy * 3 + dx] = s[sl][ty + dy][tx + dx];

        const float v0 = B[4];

        // ---- data term: conv_z^T of E planes ----
        float gd = 0.f;
        if (stride == 2) {
            int h = z >> 1;
            if ((z & 1) == 0) {
                if (z >= 2)                          gd = fmaf(pz[0], Ecol[(size_t)(h - 1) * HW], gd);
                if (h < n_slices)                    gd = fmaf(pz[2], Ecol[(size_t)h * HW], gd);
                if (z + 2 < D && h + 1 < n_slices)   gd = fmaf(pz[4], Ecol[(size_t)(h + 1) * HW], gd);
            } else {
                if (h < n_slices)                    gd = fmaf(pz[1], Ecol[(size_t)h * HW], gd);
                if (z + 1 < D && h + 1 < n_slices)   gd = fmaf(pz[3], Ecol[(size_t)(h + 1) * HW], gd);
            }
        } else {
            #pragma unroll
            for (int dz = 0; dz < 5; ++dz) {
                int zz = z + dz - 2;
                if ((unsigned)zz < (unsigned)D && (zz % stride) == 0) {
                    int pi = zz / stride;
                    if (pi < n_slices) gd = fmaf(pz[dz], Ecol[(size_t)pi * HW], gd);
                }
            }
        }

        // ---- regularizer (interior only) ----
        float greg = 0.f;
        if (interior_xy && z > 0 && z < D - 1) {
            #pragma unroll
            for (int j = 0; j < 9; ++j) {
                const int dy = j / 3 - 1, dx = j % 3 - 1;
                const int d2a = dy * dy + dx * dx + 1;
                const float wa = (d2a == 1) ? w1 : ((d2a == 2) ? w2 : w3);
                {
                    float dv = v0 - A[j];
                    float t = dv * wa;
                    greg += t * rsqrtf(fmaf(dv, t, 1.0f));
                }
                {
                    float dv = v0 - C[j];
                    float t = dv * wa;
                    greg += t * rsqrtf(fmaf(dv, t, 1.0f));
                }
                if (j != 4) {
                    const int d2b = dy * dy + dx * dx;
                    const float wb = (d2b == 1) ? w1 : ((d2b == 2) ? w2 : w3);
                    float dv = v0 - B[j];
                    float t = dv * wb;
                    greg += t * rsqrtf(fmaf(dv, t, 1.0f));
                }
            }
        }

        float xn = v0 - ALPHA * (gd + BETA * greg);
        if (do_relu) xn = fmaxf(xn, 0.f);
        outcol[(size_t)z * HW] = xn;

        #pragma unroll
        for (int j = 0; j < 9; ++j) { A[j] = B[j]; B[j] = C[j]; }
    }
}

// ---------------------------------------------------------------------------
extern "C" void kernel_launch(void* const* d_in, const int* in_sizes, int n_in,
                              void* d_out, int out_size) {
    const float* slices = (const float*)d_in[1];
    const float* volume = (const float*)d_in[2];
    const float* psf    = (const float*)d_in[3];
    const int* stridep  = (const int*)d_in[4];

    int D = (int)lround(cbrt((double)out_size));   // 192
    int H = D, W = D;
    int n_slices = in_sizes[1] / (H * W);

    float *pE, *pA, *pB;
    cudaGetSymbolAddress((void**)&pE, d_E);
    cudaGetSymbolAddress((void**)&pA, d_A);
    cudaGetSymbolAddress((void**)&pB, d_B);

    init_p_kernel<<<1, 32>>>(psf);

    dim3 blkE(32, 8, 1);
    dim3 grid_E((W + 31) / 32, (H + 31) / 32, n_slices);
    dim3 blkU(32, 8, 1);
    dim3 grid_up((W + 31) / 32, (H + 7) / 8, (D + UPD_CHUNK - 1) / UPD_CHUNK);

    for (int it = 0; it < N_ITER; ++it) {
        const float* xin = (it == 0) ? volume : ((it & 1) ? pA : pB);
        float* xout = (it == N_ITER - 1) ? (float*)d_out
                                         : ((it & 1) ? pB : pA);
        int do_relu = (it == N_ITER - 1) ? 1 : 0;

        fused_E_kernel<<<grid_E, blkE>>>(xin, slices, pE, stridep,
                                         D, H, W, n_slices);
        update_roll_kernel<<<grid_up, blkU>>>(xin, pE, xout, stridep, n_slices,
                                              D, H, W, do_relu);
    }
}

// round 5
// speedup vs baseline: 2.0187x; 1.1521x over previous
#include <cuda_runtime.h>
#include <math.h>

#define N_ITER 10
#define UPD_CHUNK 24

static __device__ float d_p[5];                     // separable 1D psf
static __device__ float d_E[96 * 192 * 192];        // conv_xy(residual) planes
static __device__ float d_A[192 * 192 * 192];       // ping
static __device__ float d_B[192 * 192 * 192];       // pong

// ---------------------------------------------------------------------------
__global__ void init_p_kernel(const float* __restrict__ psf) {
    int i = threadIdx.x;
    if (i < 5) {
        float s = 0.f;
        for (int j = 0; j < 25; ++j) s += psf[i * 25 + j];
        d_p[i] = s;
    }
}

// ===========================================================================
// Specialized kernels: compile-time D,H,W,NS (192,192,192,96); int offsets.
// ===========================================================================

template <int D, int H, int W, int NS>
__global__ __launch_bounds__(256) void fused_E_t(
    const float* __restrict__ x, const float* __restrict__ slices,
    float* __restrict__ E, const int* __restrict__ stridep) {
    constexpr int HW = H * W;
    __shared__ float sZ[40][44];
    __shared__ float sA[40][36];
    __shared__ float sF[36][36];
    __shared__ float sB[36][33];

    const int i = blockIdx.z;
    const int zi = i * (*stridep);
    const int x0 = blockIdx.x * 32, y0 = blockIdx.y * 32;
    const int tx = threadIdx.x, ty = threadIdx.y;

    const float p0 = d_p[0], p1 = d_p[1], p2 = d_p[2], p3 = d_p[3], p4 = d_p[4];

    const int z0 = zi - 2;
    const bool intZ  = (z0 >= 0) && (z0 + 4 < D);
    const bool intXY = (x0 >= 4) && (x0 + 36 <= W) && (y0 >= 4) && (y0 + 36 <= H);

    // ---- step 1: z-combine into sZ (40 x 40), halo 4 ----
    if (intZ && intXY) {
        const float* base = x + z0 * HW + (y0 - 4) * W + (x0 - 4);
        #pragma unroll
        for (int k = 0; k < 5; ++k) {
            const int r = ty + 8 * k;
            const float* rowp = base + r * W;
            {
                const float* col = rowp + tx;
                sZ[r][tx] = p0 * col[0]      + p1 * col[HW]     + p2 * col[2 * HW]
                          + p3 * col[3 * HW] + p4 * col[4 * HW];
            }
            if (tx < 8) {
                const float* col = rowp + 32 + tx;
                sZ[r][32 + tx] = p0 * col[0]      + p1 * col[HW]     + p2 * col[2 * HW]
                               + p3 * col[3 * HW] + p4 * col[4 * HW];
            }
        }
    } else {
        const bool zok0 = (z0 >= 0), zok1 = (z0 + 1 >= 0);
        const bool zok2 = (z0 + 2 >= 0) && (z0 + 2 < D);
        const bool zok3 = (z0 + 3 < D), zok4 = (z0 + 4 < D);
        #pragma unroll
        for (int k = 0; k < 5; ++k) {
            const int r = ty + 8 * k;
            const int gy = y0 - 4 + r;
            const bool okY = (unsigned)gy < (unsigned)H;
            #pragma unroll
            for (int b = 0; b < 2; ++b) {
                const int c = b * 32 + tx;
                if (b == 1 && tx >= 8) break;
                const int gx = x0 - 4 + c;
                float acc = 0.f;
                if (okY && (unsigned)gx < (unsigned)W) {
                    const float* col = x + gy * W + gx + z0 * HW;
                    if (zok0) acc = fmaf(p0, col[0], acc);
                    if (zok1) acc = fmaf(p1, col[HW], acc);
                    if (zok2) acc = fmaf(p2, col[2 * HW], acc);
                    if (zok3) acc = fmaf(p3, col[3 * HW], acc);
                    if (zok4) acc = fmaf(p4, col[4 * HW], acc);
                }
                sZ[r][c] = acc;
            }
        }
    }
    __syncthreads();

    // ---- step 2: x-conv into sA (40 x 36) ----
    #pragma unroll
    for (int k = 0; k < 5; ++k) {
        const int r = ty + 8 * k;
        sA[r][tx] = p0 * sZ[r][tx]     + p1 * sZ[r][tx + 1] + p2 * sZ[r][tx + 2]
                  + p3 * sZ[r][tx + 3] + p4 * sZ[r][tx + 4];
        if (tx < 4) {
            const int c = 32 + tx;
            sA[r][c] = p0 * sZ[r][c]     + p1 * sZ[r][c + 1] + p2 * sZ[r][c + 2]
                     + p3 * sZ[r][c + 3] + p4 * sZ[r][c + 4];
        }
    }
    __syncthreads();

    // ---- step 3: y-conv + subtract slice into sF (36 x 36) ----
    {
        const float* sl = slices + i * HW;
        if (intXY) {
            const float* sbase = sl + (y0 - 2) * W + (x0 - 2);
            #pragma unroll
            for (int k = 0; k < 5; ++k) {
                const int r = (k < 4) ? (ty + 8 * k) : (32 + ty);
                if (k == 4 && ty >= 4) break;
                sF[r][tx] = p0 * sA[r][tx]     + p1 * sA[r + 1][tx] + p2 * sA[r + 2][tx]
                          + p3 * sA[r + 3][tx] + p4 * sA[r + 4][tx]
                          - sbase[r * W + tx];
                if (tx < 4) {
                    const int c = 32 + tx;
                    sF[r][c] = p0 * sA[r][c]     + p1 * sA[r + 1][c] + p2 * sA[r + 2][c]
                             + p3 * sA[r + 3][c] + p4 * sA[r + 4][c]
                             - sbase[r * W + c];
                }
            }
        } else {
            #pragma unroll
            for (int k = 0; k < 5; ++k) {
                const int r = (k < 4) ? (ty + 8 * k) : (32 + ty);
                if (k == 4 && ty >= 4) break;
                const int gy = y0 - 2 + r;
                const bool okY = (unsigned)gy < (unsigned)H;
                #pragma unroll
                for (int b = 0; b < 2; ++b) {
                    const int c = b * 32 + tx;
                    if (b == 1 && tx >= 4) break;
                    const int gx = x0 - 2 + c;
                    float v = 0.f;
                    if (okY && (unsigned)gx < (unsigned)W) {
                        v = p0 * sA[r][c]     + p1 * sA[r + 1][c] + p2 * sA[r + 2][c]
                          + p3 * sA[r + 3][c] + p4 * sA[r + 4][c]
                          - sl[gy * W + gx];
                    }
                    sF[r][c] = v;
                }
            }
        }
    }
    __syncthreads();

    // ---- step 4: x-conv into sB (36 x 32) ----
    #pragma unroll
    for (int k = 0; k < 5; ++k) {
        const int r = (k < 4) ? (ty + 8 * k) : (32 + ty);
        if (k == 4 && ty >= 4) break;
        sB[r][tx] = p0 * sF[r][tx]     + p1 * sF[r][tx + 1] + p2 * sF[r][tx + 2]
                  + p3 * sF[r][tx + 3] + p4 * sF[r][tx + 4];
    }
    __syncthreads();

    // ---- step 5: y-conv, store E (32 x 32); H,W multiples of 32 ----
    {
        float* Ei = E + i * HW + y0 * W + x0;
        #pragma unroll
        for (int k = 0; k < 4; ++k) {
            const int r = ty + 8 * k;
            Ei[r * W + tx] = p0 * sB[r][tx]     + p1 * sB[r + 1][tx] + p2 * sB[r + 2][tx]
                           + p3 * sB[r + 3][tx] + p4 * sB[r + 4][tx];
        }
    }
}

// ---------------------------------------------------------------------------
template <int D, int H, int W, int NS>
__global__ __launch_bounds__(256, 4) void update_t(
    const float* __restrict__ xin, const float* __restrict__ E,
    float* __restrict__ xout, const int* __restrict__ stridep, int do_relu) {
    constexpr int HW = H * W;
    __shared__ float s[3][10][36];

    const int x0 = blockIdx.x * 32, y0 = blockIdx.y * 8;
    const int zb = blockIdx.z * UPD_CHUNK;        // always even (24 | zb)
    const int tx = threadIdx.x, ty = threadIdx.y;
    const int tid = ty * 32 + tx;
    const int y = y0 + ty, x = x0 + tx;
    const int stride = *stridep;

    const float p0 = d_p[0], p1 = d_p[1], p2 = d_p[2], p3 = d_p[3], p4 = d_p[4];

    const float w1 = (float)(1.0 / (1.0 * 0.1 * 0.1));
    const float w2 = (float)(1.0 / (2.0 * 0.1 * 0.1));
    const float w3 = (float)(1.0 / (3.0 * 0.1 * 0.1));

    // hoisted cooperative-load geometry (10*34 = 340 slots)
    const int ly0 = tid / 34, lx0 = tid % 34;
    const int gy0 = y0 - 1 + ly0, gx0 = x0 - 1 + lx0;
    const bool ok0 = (unsigned)gy0 < (unsigned)H && (unsigned)gx0 < (unsigned)W;
    const int off0 = ok0 ? (gy0 * W + gx0) : 0;

    const int i1 = tid + 256;
    const bool has1 = (i1 < 340);
    const int ly1 = has1 ? i1 / 34 : 0, lx1 = has1 ? i1 % 34 : 0;
    const int gy1 = y0 - 1 + ly1, gx1 = x0 - 1 + lx1;
    const bool ok1 = has1 && (unsigned)gy1 < (unsigned)H && (unsigned)gx1 < (unsigned)W;
    const int off1 = ok1 ? (gy1 * W + gx1) : 0;

    auto loadPlane = [&](int z, int sl) {
        const bool zok = (unsigned)z < (unsigned)D;
        const int zo = (zok ? z : 0) * HW;
        s[sl][ly0][lx0] = (zok && ok0) ? xin[zo + off0] : 0.f;
        if (has1) s[sl][ly1][lx1] = (zok && ok1) ? xin[zo + off1] : 0.f;
    };

    // prime ring: planes zb-1, zb
    const int sl_m1 = (zb + 2) % 3;   // == (zb-1) mod 3
    const int sl_0  = zb % 3;
    loadPlane(zb - 1, sl_m1);
    loadPlane(zb, sl_0);
    __syncthreads();

    float A[9], B[9];
    #pragma unroll
    for (int dy = 0; dy < 3; ++dy)
        #pragma unroll
        for (int dx = 0; dx < 3; ++dx) {
            A[dy * 3 + dx] = s[sl_m1][ty + dy][tx + dx];
            B[dy * 3 + dx] = s[sl_0][ty + dy][tx + dx];
        }

    const bool interior_xy = (y > 0 && y < H - 1 && x > 0 && x < W - 1);
    const int eo = y * W + x;
    const float* Ecol = E + eo;
    float* outcol = xout + eo;
    const float ALPHA = 0.5f;
    const float BETA = (float)(0.02 * 0.1 * 0.1);

    // regularizer body on rolled registers
    auto regTerm = [&](const float* Av, const float* Bv, const float* Cv) -> float {
        float greg = 0.f;
        const float v0 = Bv[4];
        #pragma unroll
        for (int j = 0; j < 9; ++j) {
            const int dy = j / 3 - 1, dx = j % 3 - 1;
            const int d2a = dy * dy + dx * dx + 1;
            const float wa = (d2a == 1) ? w1 : ((d2a == 2) ? w2 : w3);
            {
                float dv = v0 - Av[j];
                float t = dv * wa;
                greg += t * rsqrtf(fmaf(dv, t, 1.0f));
            }
            {
                float dv = v0 - Cv[j];
                float t = dv * wa;
                greg += t * rsqrtf(fmaf(dv, t, 1.0f));
            }
            if (j != 4) {
                const int d2b = dy * dy + dx * dx;
                const float wb = (d2b == 1) ? w1 : ((d2b == 2) ? w2 : w3);
                float dv = v0 - Bv[j];
                float t = dv * wb;
                greg += t * rsqrtf(fmaf(dv, t, 1.0f));
            }
        }
        return greg;
    };

    int slNext = (zb + 1) % 3;
    const int zend = (zb + UPD_CHUNK < D) ? (zb + UPD_CHUNK) : D;

    if (stride == 2) {
        int h = zb >> 1;
        float eA = (h >= 1) ? Ecol[(h - 1) * HW] : 0.f;
        float eB = (h < NS) ? Ecol[h * HW] : 0.f;
        float eC = (h + 1 < NS) ? Ecol[(h + 1) * HW] : 0.f;

        for (int z = zb; z < zend; z += 2, ++h) {
            // ---- even z ----
            {
                const int sl = slNext; slNext = (slNext == 2) ? 0 : slNext + 1;
                loadPlane(z + 1, sl);
                __syncthreads();
                float C[9];
                #pragma unroll
                for (int dy = 0; dy < 3; ++dy)
                    #pragma unroll
                    for (int dx = 0; dx < 3; ++dx)
                        C[dy * 3 + dx] = s[sl][ty + dy][tx + dx];

                float gd = fmaf(p0, eA, fmaf(p2, eB, p4 * eC));
                float greg = 0.f;
                if (interior_xy && z > 0 && z < D - 1) greg = regTerm(A, B, C);
                float xn = B[4] - ALPHA * (gd + BETA * greg);
                if (do_relu) xn = fmaxf(xn, 0.f);
                outcol[z * HW] = xn;
                #pragma unroll
                for (int j = 0; j < 9; ++j) { A[j] = B[j]; B[j] = C[j]; }
            }
            // ---- odd z+1 ----
            {
                const int sl = slNext; slNext = (slNext == 2) ? 0 : slNext + 1;
                loadPlane(z + 2, sl);
                __syncthreads();
                float C[9];
                #pragma unroll
                for (int dy = 0; dy < 3; ++dy)
                    #pragma unroll
                    for (int dx = 0; dx < 3; ++dx)
                        C[dy * 3 + dx] = s[sl][ty + dy][tx + dx];

                float gd = fmaf(p1, eB, p3 * eC);
                float greg = 0.f;
                if (interior_xy && z + 1 < D - 1) greg = regTerm(A, B, C);
                float xn = B[4] - ALPHA * (gd + BETA * greg);
                if (do_relu) xn = fmaxf(xn, 0.f);
                outcol[(z + 1) * HW] = xn;
                #pragma unroll
                for (int j = 0; j < 9; ++j) { A[j] = B[j]; B[j] = C[j]; }
            }
            // roll E planes
            eA = eB; eB = eC;
            eC = (h + 2 < NS) ? Ecol[(h + 2) * HW] : 0.f;
        }
    } else {
        const float pz[5] = {p0, p1, p2, p3, p4};
        for (int z = zb; z < zend; ++z) {
            const int sl = slNext; slNext = (slNext == 2) ? 0 : slNext + 1;
            loadPlane(z + 1, sl);
            __syncthreads();
            float C[9];
            #pragma unroll
            for (int dy = 0; dy < 3; ++dy)
                #pragma unroll
                for (int dx = 0; dx < 3; ++dx)
                    C[dy * 3 + dx] = s[sl][ty + dy][tx + dx];

            float gd = 0.f;
            #pragma unroll
            for (int dz = 0; dz < 5; ++dz) {
                int zz = z + dz - 2;
                if ((unsigned)zz < (unsigned)D && (zz % stride) == 0) {
                    int pi = zz / stride;
                    if (pi < NS) gd = fmaf(pz[dz], Ecol[pi * HW], gd);
                }
            }
            float greg = 0.f;
            if (interior_xy && z > 0 && z < D - 1) greg = regTerm(A, B, C);
            float xn = B[4] - ALPHA * (gd + BETA * greg);
            if (do_relu) xn = fmaxf(xn, 0.f);
            outcol[z * HW] = xn;
            #pragma unroll
            for (int j = 0; j < 9; ++j) { A[j] = B[j]; B[j] = C[j]; }
        }
    }
}

// ===========================================================================
// Generic fallback kernels (runtime dims) — as validated in R4.
// ===========================================================================

__global__ __launch_bounds__(256) void fused_E_gen(
    const float* __restrict__ x, const float* __restrict__ slices,
    float* __restrict__ E, const int* __restrict__ stridep,
    int D, int H, int W, int n_slices) {
    __shared__ float sZ[40][44];
    __shared__ float sA[40][36];
    __shared__ float sF[36][36];
    __shared__ float sB[36][33];

    const int i = blockIdx.z;
    const int zi = i * (*stridep);
    const int x0 = blockIdx.x * 32, y0 = blockIdx.y * 32;
    const int tx = threadIdx.x, ty = threadIdx.y;
    const size_t HW = (size_t)H * W;

    const float p0 = d_p[0], p1 = d_p[1], p2 = d_p[2], p3 = d_p[3], p4 = d_p[4];

    {
        const int z0 = zi - 2;
        const bool zok0 = (z0 >= 0), zok1 = (z0 + 1 >= 0);
        const bool zok2 = (z0 + 2 >= 0) && (z0 + 2 < D);
        const bool zok3 = (z0 + 3 < D), zok4 = (z0 + 4 < D);
        #pragma unroll
        for (int k = 0; k < 5; ++k) {
            const int r = ty + 8 * k;
            const int gy = y0 - 4 + r;
            const bool okY = (unsigned)gy < (unsigned)H;
            #pragma unroll
            for (int b = 0; b < 2; ++b) {
                const int c = b * 32 + tx;
                if (b == 1 && tx >= 8) break;
                const int gx = x0 - 4 + c;
                float acc = 0.f;
                if (okY && (unsigned)gx < (unsigned)W) {
                    const float* col = x + (size_t)gy * W + gx + (size_t)z0 * HW;
                    if (zok0) acc = fmaf(p0, col[0], acc);
                    if (zok1) acc = fmaf(p1, col[HW], acc);
                    if (zok2) acc = fmaf(p2, col[2 * HW], acc);
                    if (zok3) acc = fmaf(p3, col[3 * HW], acc);
                    if (zok4) acc = fmaf(p4, col[4 * HW], acc);
                }
                sZ[r][c] = acc;
            }
        }
    }
    __syncthreads();

    #pragma unroll
    for (int k = 0; k < 5; ++k) {
        const int r = ty + 8 * k;
        sA[r][tx] = p0 * sZ[r][tx]     + p1 * sZ[r][tx + 1] + p2 * sZ[r][tx + 2]
                  + p3 * sZ[r][tx + 3] + p4 * sZ[r][tx + 4];
        if (tx < 4) {
            const int c = 32 + tx;
            sA[r][c] = p0 * sZ[r][c]     + p1 * sZ[r][c + 1] + p2 * sZ[r][c + 2]
                     + p3 * sZ[r][c + 3] + p4 * sZ[r][c + 4];
        }
    }
    __syncthreads();

    {
        const float* sl = slices + (size_t)i * HW;
        #pragma unroll
        for (int k = 0; k < 5; ++k) {
            const int r = (k < 4) ? (ty + 8 * k) : (32 + ty);
            if (k == 4 && ty >= 4) break;
            const int gy = y0 - 2 + r;
            const bool okY = (unsigned)gy < (unsigned)H;
            #pragma unroll
            for (int b = 0; b < 2; ++b) {
                const int c = b * 32 + tx;
                if (b == 1 && tx >= 4) break;
                const int gx = x0 - 2 + c;
                float v = 0.f;
                if (okY && (unsigned)gx < (unsigned)W) {
                    v = p0 * sA[r][c]     + p1 * sA[r + 1][c] + p2 * sA[r + 2][c]
                      + p3 * sA[r + 3][c] + p4 * sA[r + 4][c]
                      - sl[(size_t)gy * W + gx];
                }
                sF[r][c] = v;
            }
        }
    }
    __syncthreads();

    #pragma unroll
    for (int k = 0; k < 5; ++k) {
        const int r = (k < 4) ? (ty + 8 * k) : (32 + ty);
        if (k == 4 && ty >= 4) break;
        sB[r][tx] = p0 * sF[r][tx]     + p1 * sF[r][tx + 1] + p2 * sF[r][tx + 2]
                  + p3 * sF[r][tx + 3] + p4 * sF[r][tx + 4];
    }
    __syncthreads();

    {
        float* Ei = E + (size_t)i * HW;
        #pragma unroll
        for (int k = 0; k < 4; ++k) {
            const int r = ty + 8 * k;
            const int gy = y0 + r, gx = x0 + tx;
            if (gy < H && gx < W) {
                Ei[(size_t)gy * W + gx] =
                      p0 * sB[r][tx]     + p1 * sB[r + 1][tx] + p2 * sB[r + 2][tx]
                    + p3 * sB[r + 3][tx] + p4 * sB[r + 4][tx];
            }
        }
    }
}

__global__ __launch_bounds__(256, 4) void update_gen(
    const float* __restrict__ xin, const float* __restrict__ E,
    float* __restrict__ xout, const int* __restrict__ stridep,
    int n_slices, int D, int H, int W, int do_relu) {
    __shared__ float s[3][10][36];

    const int x0 = blockIdx.x * 32, y0 = blockIdx.y * 8;
    const int zb = blockIdx.z * UPD_CHUNK;
    const int tx = threadIdx.x, ty = threadIdx.y;
    const int tid = ty * 32 + tx;
    const size_t HW = (size_t)H * W;
    const int y = y0 + ty, x = x0 + tx;
    const int stride = *stridep;

    const float p0 = d_p[0], p1 = d_p[1], p2 = d_p[2], p3 = d_p[3], p4 = d_p[4];
    const float pz[5] = {p0, p1, p2, p3, p4};
    const float w1 = (float)(1.0 / (1.0 * 0.1 * 0.1));
    const float w2 = (float)(1.0 / (2.0 * 0.1 * 0.1));
    const float w3 = (float)(1.0 / (3.0 * 0.1 * 0.1));

    const int ly0 = tid / 34, lx0 = tid % 34;
    const int gy0 = y0 - 1 + ly0, gx0 = x0 - 1 + lx0;
    const bool ok0 = (unsigned)gy0 < (unsigned)H && (unsigned)gx0 < (unsigned)W;
    const size_t off0 = ok0 ? ((size_t)gy0 * W + gx0) : 0;
    const int i1 = tid + 256;
    const bool has1 = (i1 < 340);
    const int ly1 = has1 ? i1 / 34 : 0, lx1 = has1 ? i1 % 34 : 0;
    const int gy1 = y0 - 1 + ly1, gx1 = x0 - 1 + lx1;
    const bool ok1 = has1 && (unsigned)gy1 < (unsigned)H && (unsigned)gx1 < (unsigned)W;
    const size_t off1 = ok1 ? ((size_t)gy1 * W + gx1) : 0;

    auto loadPlane = [&](int z, int sl) {
        const bool zok = (unsigned)z < (unsigned)D;
        const size_t zo = (size_t)(zok ? z : 0) * HW;
        s[sl][ly0][lx0] = (zok && ok0) ? xin[zo + off0] : 0.f;
        if (has1) s[sl][ly1][lx1] = (zok && ok1) ? xin[zo + off1] : 0.f;
    };

    const int sl_m1 = ((zb - 1) % 3 + 3) % 3;
    const int sl_0  = zb % 3;
    loadPlane(zb - 1, sl_m1);
    loadPlane(zb, sl_0);
    __syncthreads();

    float A[9], B[9];
    #pragma unroll
    for (int dy = 0; dy < 3; ++dy)
        #pragma unroll
        for (int dx = 0; dx < 3; ++dx) {
            A[dy * 3 + dx] = s[sl_m1][ty + dy][tx + dx];
            B[dy * 3 + dx] = s[sl_0][ty + dy][tx + dx];
        }

    const bool interior_xy = (y > 0 && y < H - 1 && x > 0 && x < W - 1);
    const size_t eo = (size_t)y * W + x;
    const float* Ecol = E + eo;
    float* outcol = xout + eo;
    const float ALPHA = 0.5f;
    const float BETA = (float)(0.02 * 0.1 * 0.1);

    int zend = zb + UPD_CHUNK;
    if (zend > D) zend = D;

    for (int z = zb; z < zend; ++z) {
        const int sl = (z + 1) % 3;
        loadPlane(z + 1, sl);
        __syncthreads();

        float C[9];
        #pragma unroll
        for (int dy = 0; dy < 3; ++dy)
            #pragma unroll
            for (int dx = 0; dx < 3; ++dx)
                C[dy * 3 + dx] = s[sl][ty + dy][tx + dx];

        const float v0 = B[4];
        float gd = 0.f;
        #pragma unroll
        for (int dz = 0; dz < 5; ++dz) {
            int zz = z + dz - 2;
            if ((unsigned)zz < (unsigned)D && (zz % stride) == 0) {
                int pi = zz / stride;
                if (pi < n_slices) gd = fmaf(pz[dz], Ecol[(size_t)pi * HW], gd);
            }
        }

        float greg = 0.f;
        if (interior_xy && z > 0 && z < D - 1) {
            #pragma unroll
            for (int j = 0; j < 9; ++j) {
                const int dy = j / 3 - 1, dx = j % 3 - 1;
                const int d2a = dy * dy + dx * dx + 1;
                const float wa = (d2a == 1) ? w1 : ((d2a == 2) ? w2 : w3);
                { float dv = v0 - A[j]; float t = dv * wa; greg += t * rsqrtf(fmaf(dv, t, 1.0f)); }
                { float dv = v0 - C[j]; float t = dv * wa; greg += t * rsqrtf(fmaf(dv, t, 1.0f)); }
                if (j != 4) {
                    const int d2b = dy * dy + dx * dx;
                    const float wb = (d2b == 1) ? w1 : ((d2b == 2) ? w2 : w3);
                    float dv = v0 - B[j]; float t = dv * wb;
                    greg += t * rsqrtf(fmaf(dv, t, 1.0f));
                }
            }
        }

        float xn = v0 - ALPHA * (gd + BETA * greg);
        if (do_relu) xn = fmaxf(xn, 0.f);
        outcol[(size_t)z * HW] = xn;

        #pragma unroll
        for (int j = 0; j < 9; ++j) { A[j] = B[j]; B[j] = C[j]; }
    }
}

// ---------------------------------------------------------------------------
extern "C" void kernel_launch(void* const* d_in, const int* in_sizes, int n_in,
                              void* d_out, int out_size) {
    const float* slices = (const float*)d_in[1];
    const float* volume = (const float*)d_in[2];
    const float* psf    = (const float*)d_in[3];
    const int* stridep  = (const int*)d_in[4];

    int D = (int)lround(cbrt((double)out_size));   // 192
    int H = D, W = D;
    int n_slices = in_sizes[1] / (H * W);

    float *pE, *pA, *pB;
    cudaGetSymbolAddress((void**)&pE, d_E);
    cudaGetSymbolAddress((void**)&pA, d_A);
    cudaGetSymbolAddress((void**)&pB, d_B);

    init_p_kernel<<<1, 32>>>(psf);

    const bool spec = (D == 192 && H == 192 && W == 192 && n_slices == 96);

    dim3 blkE(32, 8, 1);
    dim3 grid_E((W + 31) / 32, (H + 31) / 32, n_slices);
    dim3 blkU(32, 8, 1);
    dim3 grid_up((W + 31) / 32, (H + 7) / 8, (D + UPD_CHUNK - 1) / UPD_CHUNK);

    for (int it = 0; it < N_ITER; ++it) {
        const float* xin = (it == 0) ? volume : ((it & 1) ? pA : pB);
        float* xout = (it == N_ITER - 1) ? (float*)d_out
                                         : ((it & 1) ? pB : pA);
        int do_relu = (it == N_ITER - 1) ? 1 : 0;

        if (spec) {
            fused_E_t<192, 192, 192, 96><<<grid_E, blkE>>>(xin, slices, pE, stridep);
            update_t<192, 192, 192, 96><<<grid_up, blkU>>>(xin, pE, xout, stridep, do_relu);
        } else {
            fused_E_gen<<<grid_E, blkE>>>(xin, slices, pE, stridep, D, H, W, n_slices);
            update_gen<<<grid_up, blkU>>>(xin, pE, xout, stridep, n_slices, D, H, W, do_relu);
        }
    }
}

// round 6
// speedup vs baseline: 2.0825x; 1.0316x over previous
#include <cuda_runtime.h>
#include <math.h>

#define N_ITER 10
#define UPD_CHUNK 24

static __device__ float d_p[5];                     // separable 1D psf
static __device__ float d_E[96 * 192 * 192];        // conv_xy(residual) planes
static __device__ float d_A[192 * 192 * 192];       // ping
static __device__ float d_B[192 * 192 * 192];       // pong

// ---------------------------------------------------------------------------
__global__ void init_p_kernel(const float* __restrict__ psf) {
    int i = threadIdx.x;
    if (i < 5) {
        float s = 0.f;
        for (int j = 0; j < 25; ++j) s += psf[i * 25 + j];
        d_p[i] = s;
    }
}

// ===========================================================================
// Specialized kernels: compile-time D,H,W,NS (192,192,192,96); int offsets.
// ===========================================================================

// fused_E, 2 slices per block. For slice pair (iA, iA+1):
//   sZ[s] = conv_z(x) at plane zi_s    (40x40 halo tile) — shared 7-plane load
//   sA[s] = conv_x(sZ[s])              (40x36)
//   sF[s] = conv_y(sA[s]) - slices     (36x36)   [overlays sZ[s]]
//   sB[s] = conv_x(sF[s])              (36x32)   [overlays sA[s]]
//   E     = conv_y(sB[s])              (32x32 output each)
template <int D, int H, int W, int NS>
__global__ __launch_bounds__(256) void fused_E2_t(
    const float* __restrict__ x, const float* __restrict__ slices,
    float* __restrict__ E, const int* __restrict__ stridep) {
    constexpr int HW = H * W;
    __shared__ float bufZ[2][40][42];   // stage1 out; later overlaid by sF (36x37)
    __shared__ float bufA[2][40][36];   // stage2 out; later overlaid by sB (36x33)

    const int pr = blockIdx.z;
    const int stride = *stridep;
    const int iA = 2 * pr;
    const int ziA = iA * stride;
    const int x0 = blockIdx.x * 32, y0 = blockIdx.y * 32;
    const int tx = threadIdx.x, ty = threadIdx.y;

    const float p0 = d_p[0], p1 = d_p[1], p2 = d_p[2], p3 = d_p[3], p4 = d_p[4];

    const bool intXY = (x0 >= 4) && (x0 + 36 <= W) && (y0 >= 4) && (y0 + 36 <= H);

    // ---- stage 1: z-combine both slices ----
    if (stride == 2) {
        const int q0 = ziA - 2;                  // planes q0 .. q0+6
        const bool intZ = (q0 >= 0) && (ziA + 4 < D);
        if (intZ && intXY) {
            const float* base = x + q0 * HW + (y0 - 4) * W + (x0 - 4);
            #pragma unroll
            for (int k = 0; k < 5; ++k) {
                const int r = ty + 8 * k;
                const float* rowp = base + r * W;
                #pragma unroll
                for (int b = 0; b < 2; ++b) {
                    if (b == 1 && tx >= 8) break;
                    const int c = b * 32 + tx;
                    const float* col = rowp + c;
                    const float v0 = col[0],      v1 = col[HW],     v2 = col[2 * HW];
                    const float v3 = col[3 * HW], v4 = col[4 * HW], v5 = col[5 * HW];
                    const float v6 = col[6 * HW];
                    bufZ[0][r][c] = p0 * v0 + p1 * v1 + p2 * v2 + p3 * v3 + p4 * v4;
                    bufZ[1][r][c] = p0 * v2 + p1 * v3 + p2 * v4 + p3 * v5 + p4 * v6;
                }
            }
        } else {
            bool qok[7];
            #pragma unroll
            for (int j = 0; j < 7; ++j) qok[j] = (unsigned)(q0 + j) < (unsigned)D;
            #pragma unroll
            for (int k = 0; k < 5; ++k) {
                const int r = ty + 8 * k;
                const int gy = y0 - 4 + r;
                const bool okY = (unsigned)gy < (unsigned)H;
                #pragma unroll
                for (int b = 0; b < 2; ++b) {
                    if (b == 1 && tx >= 8) break;
                    const int c = b * 32 + tx;
                    const int gx = x0 - 4 + c;
                    const bool okXY = okY && (unsigned)gx < (unsigned)W;
                    const float* col = x + gy * W + gx;
                    float v[7];
                    #pragma unroll
                    for (int j = 0; j < 7; ++j)
                        v[j] = (okXY && qok[j]) ? col[(q0 + j) * HW] : 0.f;
                    bufZ[0][r][c] = p0 * v[0] + p1 * v[1] + p2 * v[2] + p3 * v[3] + p4 * v[4];
                    bufZ[1][r][c] = p0 * v[2] + p1 * v[3] + p2 * v[4] + p3 * v[5] + p4 * v[6];
                }
            }
        }
    } else {
        // generic stride: independent 5-plane loads per slice
        #pragma unroll
        for (int s = 0; s < 2; ++s) {
            const int zi = (iA + s) * stride;
            const int z0 = zi - 2;
            bool zok[5];
            #pragma unroll
            for (int j = 0; j < 5; ++j) zok[j] = (unsigned)(z0 + j) < (unsigned)D;
            #pragma unroll
            for (int k = 0; k < 5; ++k) {
                const int r = ty + 8 * k;
                const int gy = y0 - 4 + r;
                const bool okY = (unsigned)gy < (unsigned)H;
                #pragma unroll
                for (int b = 0; b < 2; ++b) {
                    if (b == 1 && tx >= 8) break;
                    const int c = b * 32 + tx;
                    const int gx = x0 - 4 + c;
                    const bool okXY = okY && (unsigned)gx < (unsigned)W;
                    const float* col = x + gy * W + gx;
                    float acc = 0.f;
                    if (okXY) {
                        if (zok[0]) acc = fmaf(p0, col[(z0 + 0) * HW], acc);
                        if (zok[1]) acc = fmaf(p1, col[(z0 + 1) * HW], acc);
                        if (zok[2]) acc = fmaf(p2, col[(z0 + 2) * HW], acc);
                        if (zok[3]) acc = fmaf(p3, col[(z0 + 3) * HW], acc);
                        if (zok[4]) acc = fmaf(p4, col[(z0 + 4) * HW], acc);
                    }
                    bufZ[s][r][c] = acc;
                }
            }
        }
    }
    __syncthreads();

    // ---- stage 2: x-conv into bufA (40 x 36) ----
    #pragma unroll
    for (int s = 0; s < 2; ++s) {
        #pragma unroll
        for (int k = 0; k < 5; ++k) {
            const int r = ty + 8 * k;
            bufA[s][r][tx] = p0 * bufZ[s][r][tx]     + p1 * bufZ[s][r][tx + 1]
                           + p2 * bufZ[s][r][tx + 2] + p3 * bufZ[s][r][tx + 3]
                           + p4 * bufZ[s][r][tx + 4];
            if (tx < 4) {
                const int c = 32 + tx;
                bufA[s][r][c] = p0 * bufZ[s][r][c]     + p1 * bufZ[s][r][c + 1]
                              + p2 * bufZ[s][r][c + 2] + p3 * bufZ[s][r][c + 3]
                              + p4 * bufZ[s][r][c + 4];
            }
        }
    }
    __syncthreads();

    // ---- stage 3: y-conv + subtract slice into sF (36 x 36, overlays bufZ) ----
    {
        float (*sF0)[37] = (float (*)[37]) &bufZ[0][0][0];
        float (*sF1)[37] = (float (*)[37]) &bufZ[1][0][0];
        #pragma unroll
        for (int s = 0; s < 2; ++s) {
            float (*sF)[37] = s ? sF1 : sF0;
            const float* sl = slices + (iA + s) * HW;
            if (intXY) {
                const float* sbase = sl + (y0 - 2) * W + (x0 - 2);
                #pragma unroll
                for (int k = 0; k < 5; ++k) {
                    const int r = (k < 4) ? (ty + 8 * k) : (32 + ty);
                    if (k == 4 && ty >= 4) break;
                    sF[r][tx] = p0 * bufA[s][r][tx]     + p1 * bufA[s][r + 1][tx]
                              + p2 * bufA[s][r + 2][tx] + p3 * bufA[s][r + 3][tx]
                              + p4 * bufA[s][r + 4][tx] - sbase[r * W + tx];
                    if (tx < 4) {
                        const int c = 32 + tx;
                        sF[r][c] = p0 * bufA[s][r][c]     + p1 * bufA[s][r + 1][c]
                                 + p2 * bufA[s][r + 2][c] + p3 * bufA[s][r + 3][c]
                                 + p4 * bufA[s][r + 4][c] - sbase[r * W + c];
                    }
                }
            } else {
                #pragma unroll
                for (int k = 0; k < 5; ++k) {
                    const int r = (k < 4) ? (ty + 8 * k) : (32 + ty);
                    if (k == 4 && ty >= 4) break;
                    const int gy = y0 - 2 + r;
                    const bool okY = (unsigned)gy < (unsigned)H;
                    #pragma unroll
                    for (int b = 0; b < 2; ++b) {
                        if (b == 1 && tx >= 4) break;
                        const int c = b * 32 + tx;
                        const int gx = x0 - 2 + c;
                        float v = 0.f;
                        if (okY && (unsigned)gx < (unsigned)W) {
                            v = p0 * bufA[s][r][c]     + p1 * bufA[s][r + 1][c]
                              + p2 * bufA[s][r + 2][c] + p3 * bufA[s][r + 3][c]
                              + p4 * bufA[s][r + 4][c] - sl[gy * W + gx];
                        }
                        sF[r][c] = v;
                    }
                }
            }
        }
    }
    __syncthreads();

    // ---- stage 4: x-conv into sB (36 x 32, overlays bufA) ----
    {
        float (*sF0)[37] = (float (*)[37]) &bufZ[0][0][0];
        float (*sF1)[37] = (float (*)[37]) &bufZ[1][0][0];
        float (*sB0)[33] = (float (*)[33]) &bufA[0][0][0];
        float (*sB1)[33] = (float (*)[33]) &bufA[1][0][0];
        #pragma unroll
        for (int s = 0; s < 2; ++s) {
            float (*sF)[37] = s ? sF1 : sF0;
            float (*sB)[33] = s ? sB1 : sB0;
            #pragma unroll
            for (int k = 0; k < 5; ++k) {
                const int r = (k < 4) ? (ty + 8 * k) : (32 + ty);
                if (k == 4 && ty >= 4) break;
                sB[r][tx] = p0 * sF[r][tx]     + p1 * sF[r][tx + 1] + p2 * sF[r][tx + 2]
                          + p3 * sF[r][tx + 3] + p4 * sF[r][tx + 4];
            }
        }
    }
    __syncthreads();

    // ---- stage 5: y-conv, store E (32 x 32 each); H,W multiples of 32 ----
    {
        float (*sB0)[33] = (float (*)[33]) &bufA[0][0][0];
        float (*sB1)[33] = (float (*)[33]) &bufA[1][0][0];
        #pragma unroll
        for (int s = 0; s < 2; ++s) {
            float (*sB)[33] = s ? sB1 : sB0;
            float* Ei = E + (iA + s) * HW + y0 * W + x0;
            #pragma unroll
            for (int k = 0; k < 4; ++k) {
                const int r = ty + 8 * k;
                Ei[r * W + tx] = p0 * sB[r][tx]     + p1 * sB[r + 1][tx]
                               + p2 * sB[r + 2][tx] + p3 * sB[r + 3][tx]
                               + p4 * sB[r + 4][tx];
            }
        }
    }
}

// ---------------------------------------------------------------------------
// update: 2 z per barrier, 4-slot smem ring, register-rolled neighborhoods.
template <int D, int H, int W, int NS>
__global__ __launch_bounds__(256, 4) void update2_t(
    const float* __restrict__ xin, const float* __restrict__ E,
    float* __restrict__ xout, const int* __restrict__ stridep, int do_relu) {
    constexpr int HW = H * W;
    __shared__ float s[4][10][36];

    const int x0 = blockIdx.x * 32, y0 = blockIdx.y * 8;
    const int zb = blockIdx.z * UPD_CHUNK;        // even
    const int tx = threadIdx.x, ty = threadIdx.y;
    const int tid = ty * 32 + tx;
    const int y = y0 + ty, x = x0 + tx;
    const int stride = *stridep;

    const float p0 = d_p[0], p1 = d_p[1], p2 = d_p[2], p3 = d_p[3], p4 = d_p[4];

    const float w1 = (float)(1.0 / (1.0 * 0.1 * 0.1));
    const float w2 = (float)(1.0 / (2.0 * 0.1 * 0.1));
    const float w3 = (float)(1.0 / (3.0 * 0.1 * 0.1));

    // hoisted cooperative-load geometry (10*34 = 340 slots)
    const int ly0 = tid / 34, lx0 = tid % 34;
    const int gy0 = y0 - 1 + ly0, gx0 = x0 - 1 + lx0;
    const bool ok0 = (unsigned)gy0 < (unsigned)H && (unsigned)gx0 < (unsigned)W;
    const int off0 = ok0 ? (gy0 * W + gx0) : 0;

    const int i1 = tid + 256;
    const bool has1 = (i1 < 340);
    const int ly1 = has1 ? i1 / 34 : 0, lx1 = has1 ? i1 % 34 : 0;
    const int gy1 = y0 - 1 + ly1, gx1 = x0 - 1 + lx1;
    const bool ok1 = has1 && (unsigned)gy1 < (unsigned)H && (unsigned)gx1 < (unsigned)W;
    const int off1 = ok1 ? (gy1 * W + gx1) : 0;

    auto loadPlane = [&](int z, int sl) {
        const bool zok = (unsigned)z < (unsigned)D;
        const int zo = (zok ? z : 0) * HW;
        s[sl][ly0][lx0] = (zok && ok0) ? xin[zo + off0] : 0.f;
        if (has1) s[sl][ly1][lx1] = (zok && ok1) ? xin[zo + off1] : 0.f;
    };

    loadPlane(zb - 1, (zb - 1) & 3);
    loadPlane(zb, zb & 3);
    __syncthreads();

    float A[9], B[9];
    {
        const int sm = (zb - 1) & 3, s0 = zb & 3;
        #pragma unroll
        for (int dy = 0; dy < 3; ++dy)
            #pragma unroll
            for (int dx = 0; dx < 3; ++dx) {
                A[dy * 3 + dx] = s[sm][ty + dy][tx + dx];
                B[dy * 3 + dx] = s[s0][ty + dy][tx + dx];
            }
    }

    const bool interior_xy = (y > 0 && y < H - 1 && x > 0 && x < W - 1);
    const int eo = y * W + x;
    const float* Ecol = E + eo;
    float* outcol = xout + eo;
    const float ALPHA = 0.5f;
    const float BETA = (float)(0.02 * 0.1 * 0.1);

    auto regTerm = [&](const float* Av, const float* Bv, const float* Cv) -> float {
        float greg = 0.f;
        const float v0 = Bv[4];
        #pragma unroll
        for (int j = 0; j < 9; ++j) {
            const int dy = j / 3 - 1, dx = j % 3 - 1;
            const int d2a = dy * dy + dx * dx + 1;
            const float wa = (d2a == 1) ? w1 : ((d2a == 2) ? w2 : w3);
            { float dv = v0 - Av[j]; float t = dv * wa; greg += t * rsqrtf(fmaf(dv, t, 1.0f)); }
            { float dv = v0 - Cv[j]; float t = dv * wa; greg += t * rsqrtf(fmaf(dv, t, 1.0f)); }
            if (j != 4) {
                const int d2b = dy * dy + dx * dx;
                const float wb = (d2b == 1) ? w1 : ((d2b == 2) ? w2 : w3);
                float dv = v0 - Bv[j]; float t = dv * wb;
                greg += t * rsqrtf(fmaf(dv, t, 1.0f));
            }
        }
        return greg;
    };

    const int zend = (zb + UPD_CHUNK < D) ? (zb + UPD_CHUNK) : D;

    if (stride == 2) {
        int h = zb >> 1;
        float eA = (h >= 1) ? Ecol[(h - 1) * HW] : 0.f;
        float eB = (h < NS) ? Ecol[h * HW] : 0.f;
        float eC = (h + 1 < NS) ? Ecol[(h + 1) * HW] : 0.f;

        for (int z = zb; z < zend; z += 2, ++h) {
            const int s1 = (z + 1) & 3, s2 = (z + 2) & 3;
            loadPlane(z + 1, s1);
            loadPlane(z + 2, s2);
            __syncthreads();

            float C1[9], C2[9];
            #pragma unroll
            for (int dy = 0; dy < 3; ++dy)
                #pragma unroll
                for (int dx = 0; dx < 3; ++dx) {
                    C1[dy * 3 + dx] = s[s1][ty + dy][tx + dx];
                    C2[dy * 3 + dx] = s[s2][ty + dy][tx + dx];
                }

            // ---- even z ----
            {
                float gd = fmaf(p0, eA, fmaf(p2, eB, p4 * eC));
                float greg = 0.f;
                if (interior_xy && z > 0) greg = regTerm(A, B, C1);
                float xn = B[4] - ALPHA * (gd + BETA * greg);
                if (do_relu) xn = fmaxf(xn, 0.f);
                outcol[z * HW] = xn;
            }
            // ---- odd z+1 ----
            {
                float gd = fmaf(p1, eB, p3 * eC);
                float greg = 0.f;
                if (interior_xy && z + 1 < D - 1) greg = regTerm(B, C1, C2);
                float xn = C1[4] - ALPHA * (gd + BETA * greg);
                if (do_relu) xn = fmaxf(xn, 0.f);
                outcol[(z + 1) * HW] = xn;
            }

            #pragma unroll
            for (int j = 0; j < 9; ++j) { A[j] = C1[j]; B[j] = C2[j]; }
            eA = eB; eB = eC;
            eC = (h + 2 < NS) ? Ecol[(h + 2) * HW] : 0.f;
        }
    } else {
        const float pz[5] = {p0, p1, p2, p3, p4};
        for (int z = zb; z < zend; ++z) {
            const int sl = (z + 1) & 3;
            loadPlane(z + 1, sl);
            __syncthreads();
            float C[9];
            #pragma unroll
            for (int dy = 0; dy < 3; ++dy)
                #pragma unroll
                for (int dx = 0; dx < 3; ++dx)
                    C[dy * 3 + dx] = s[sl][ty + dy][tx + dx];

            float gd = 0.f;
            #pragma unroll
            for (int dz = 0; dz < 5; ++dz) {
                int zz = z + dz - 2;
                if ((unsigned)zz < (unsigned)D && (zz % stride) == 0) {
                    int pi = zz / stride;
                    if (pi < NS) gd = fmaf(pz[dz], Ecol[pi * HW], gd);
                }
            }
            float greg = 0.f;
            if (interior_xy && z > 0 && z < D - 1) greg = regTerm(A, B, C);
            float xn = B[4] - ALPHA * (gd + BETA * greg);
            if (do_relu) xn = fmaxf(xn, 0.f);
            outcol[z * HW] = xn;
            #pragma unroll
            for (int j = 0; j < 9; ++j) { A[j] = B[j]; B[j] = C[j]; }
        }
    }
}

// ===========================================================================
// Generic fallback kernels (runtime dims) — validated in R4/R5.
// ===========================================================================

__global__ __launch_bounds__(256) void fused_E_gen(
    const float* __restrict__ x, const float* __restrict__ slices,
    float* __restrict__ E, const int* __restrict__ stridep,
    int D, int H, int W, int n_slices) {
    __shared__ float sZ[40][44];
    __shared__ float sA[40][36];
    __shared__ float sF[36][36];
    __shared__ float sB[36][33];

    const int i = blockIdx.z;
    const int zi = i * (*stridep);
    const int x0 = blockIdx.x * 32, y0 = blockIdx.y * 32;
    const int tx = threadIdx.x, ty = threadIdx.y;
    const size_t HW = (size_t)H * W;

    const float p0 = d_p[0], p1 = d_p[1], p2 = d_p[2], p3 = d_p[3], p4 = d_p[4];

    {
        const int z0 = zi - 2;
        const bool zok0 = (z0 >= 0), zok1 = (z0 + 1 >= 0);
        const bool zok2 = (z0 + 2 >= 0) && (z0 + 2 < D);
        const bool zok3 = (z0 + 3 < D), zok4 = (z0 + 4 < D);
        #pragma unroll
        for (int k = 0; k < 5; ++k) {
            const int r = ty + 8 * k;
            const int gy = y0 - 4 + r;
            const bool okY = (unsigned)gy < (unsigned)H;
            #pragma unroll
            for (int b = 0; b < 2; ++b) {
                const int c = b * 32 + tx;
                if (b == 1 && tx >= 8) break;
                const int gx = x0 - 4 + c;
                float acc = 0.f;
                if (okY && (unsigned)gx < (unsigned)W) {
                    const float* col = x + (size_t)gy * W + gx + (size_t)z0 * HW;
                    if (zok0) acc = fmaf(p0, col[0], acc);
                    if (zok1) acc = fmaf(p1, col[HW], acc);
                    if (zok2) acc = fmaf(p2, col[2 * HW], acc);
                    if (zok3) acc = fmaf(p3, col[3 * HW], acc);
                    if (zok4) acc = fmaf(p4, col[4 * HW], acc);
                }
                sZ[r][c] = acc;
            }
        }
    }
    __syncthreads();

    #pragma unroll
    for (int k = 0; k < 5; ++k) {
        const int r = ty + 8 * k;
        sA[r][tx] = p0 * sZ[r][tx]     + p1 * sZ[r][tx + 1] + p2 * sZ[r][tx + 2]
                  + p3 * sZ[r][tx + 3] + p4 * sZ[r][tx + 4];
        if (tx < 4) {
            const int c = 32 + tx;
            sA[r][c] = p0 * sZ[r][c]     + p1 * sZ[r][c + 1] + p2 * sZ[r][c + 2]
                     + p3 * sZ[r][c + 3] + p4 * sZ[r][c + 4];
        }
    }
    __syncthreads();

    {
        const float* sl = slices + (size_t)i * HW;
        #pragma unroll
        for (int k = 0; k < 5; ++k) {
            const int r = (k < 4) ? (ty + 8 * k) : (32 + ty);
            if (k == 4 && ty >= 4) break;
            const int gy = y0 - 2 + r;
            const bool okY = (unsigned)gy < (unsigned)H;
            #pragma unroll
            for (int b = 0; b < 2; ++b) {
                const int c = b * 32 + tx;
                if (b == 1 && tx >= 4) break;
                const int gx = x0 - 2 + c;
                float v = 0.f;
                if (okY && (unsigned)gx < (unsigned)W) {
                    v = p0 * sA[r][c]     + p1 * sA[r + 1][c] + p2 * sA[r + 2][c]
                      + p3 * sA[r + 3][c] + p4 * sA[r + 4][c]
                      - sl[(size_t)gy * W + gx];
                }
                sF[r][c] = v;
            }
        }
    }
    __syncthreads();

    #pragma unroll
    for (int k = 0; k < 5; ++k) {
        const int r = (k < 4) ? (ty + 8 * k) : (32 + ty);
        if (k == 4 && ty >= 4) break;
        sB[r][tx] = p0 * sF[r][tx]     + p1 * sF[r][tx + 1] + p2 * sF[r][tx + 2]
                  + p3 * sF[r][tx + 3] + p4 * sF[r][tx + 4];
    }
    __syncthreads();

    {
        float* Ei = E + (size_t)i * HW;
        #pragma unroll
        for (int k = 0; k < 4; ++k) {
            const int r = ty + 8 * k;
            const int gy = y0 + r, gx = x0 + tx;
            if (gy < H && gx < W) {
                Ei[(size_t)gy * W + gx] =
                      p0 * sB[r][tx]     + p1 * sB[r + 1][tx] + p2 * sB[r + 2][tx]
                    + p3 * sB[r + 3][tx] + p4 * sB[r + 4][tx];
            }
        }
    }
}

__global__ __launch_bounds__(256, 4) void update_gen(
    const float* __restrict__ xin, const float* __restrict__ E,
    float* __restrict__ xout, const int* __restrict__ stridep,
    int n_slices, int D, int H, int W, int do_relu) {
    __shared__ float s[3][10][36];

    const int x0 = blockIdx.x * 32, y0 = blockIdx.y * 8;
    const int zb = blockIdx.z * UPD_CHUNK;
    const int tx = threadIdx.x, ty = threadIdx.y;
    const int tid = ty * 32 + tx;
    const size_t HW = (size_t)H * W;
    const int y = y0 + ty, x = x0 + tx;
    const int stride = *stridep;

    const float p0 = d_p[0], p1 = d_p[1], p2 = d_p[2], p3 = d_p[3], p4 = d_p[4];
    const float pz[5] = {p0, p1, p2, p3, p4};
    const float w1 = (float)(1.0 / (1.0 * 0.1 * 0.1));
    const float w2 = (float)(1.0 / (2.0 * 0.1 * 0.1));
    const float w3 = (float)(1.0 / (3.0 * 0.1 * 0.1));

    const int ly0 = tid / 34, lx0 = tid % 34;
    const int gy0 = y0 - 1 + ly0, gx0 = x0 - 1 + lx0;
    const bool ok0 = (unsigned)gy0 < (unsigned)H && (unsigned)gx0 < (unsigned)W;
    const size_t off0 = ok0 ? ((size_t)gy0 * W + gx0) : 0;
    const int i1 = tid + 256;
    const bool has1 = (i1 < 340);
    const int ly1 = has1 ? i1 / 34 : 0, lx1 = has1 ? i1 % 34 : 0;
    const int gy1 = y0 - 1 + ly1, gx1 = x0 - 1 + lx1;
    const bool ok1 = has1 && (unsigned)gy1 < (unsigned)H && (unsigned)gx1 < (unsigned)W;
    const size_t off1 = ok1 ? ((size_t)gy1 * W + gx1) : 0;

    auto loadPlane = [&](int z, int sl) {
        const bool zok = (unsigned)z < (unsigned)D;
        const size_t zo = (size_t)(zok ? z : 0) * HW;
        s[sl][ly0][lx0] = (zok && ok0) ? xin[zo + off0] : 0.f;
        if (has1) s[sl][ly1][lx1] = (zok && ok1) ? xin[zo + off1] : 0.f;
    };

    const int sl_m1 = ((zb - 1) % 3 + 3) % 3;
    const int sl_0  = zb % 3;
    loadPlane(zb - 1, sl_m1);
    loadPlane(zb, sl_0);
    __syncthreads();

    float A[9], B[9];
    #pragma unroll
    for (int dy = 0; dy < 3; ++dy)
        #pragma unroll
        for (int dx = 0; dx < 3; ++dx) {
            A[dy * 3 + dx] = s[sl_m1][ty + dy][tx + dx];
            B[dy * 3 + dx] = s[sl_0][ty + dy][tx + dx];
        }

    const bool interior_xy = (y > 0 && y < H - 1 && x > 0 && x < W - 1);
    const size_t eo = (size_t)y * W + x;
    const float* Ecol = E + eo;
    float* outcol = xout + eo;
    const float ALPHA = 0.5f;
    const float BETA = (float)(0.02 * 0.1 * 0.1);

    int zend = zb + UPD_CHUNK;
    if (zend > D) zend = D;

    for (int z = zb; z < zend; ++z) {
        const int sl = (z + 1) % 3;
        loadPlane(z + 1, sl);
        __syncthreads();

        float C[9];
        #pragma unroll
        for (int dy = 0; dy < 3; ++dy)
            #pragma unroll
            for (int dx = 0; dx < 3; ++dx)
                C[dy * 3 + dx] = s[sl][ty + dy][tx + dx];

        const float v0 = B[4];
        float gd = 0.f;
        #pragma unroll
        for (int dz = 0; dz < 5; ++dz) {
            int zz = z + dz - 2;
            if ((unsigned)zz < (unsigned)D && (zz % stride) == 0) {
                int pi = zz / stride;
                if (pi < n_slices) gd = fmaf(pz[dz], Ecol[(size_t)pi * HW], gd);
            }
        }

        float greg = 0.f;
        if (interior_xy && z > 0 && z < D - 1) {
            #pragma unroll
            for (int j = 0; j < 9; ++j) {
                const int dy = j / 3 - 1, dx = j % 3 - 1;
                const int d2a = dy * dy + dx * dx + 1;
                const float wa = (d2a == 1) ? w1 : ((d2a == 2) ? w2 : w3);
                { float dv = v0 - A[j]; float t = dv * wa; greg += t * rsqrtf(fmaf(dv, t, 1.0f)); }
                { float dv = v0 - C[j]; float t = dv * wa; greg += t * rsqrtf(fmaf(dv, t, 1.0f)); }
                if (j != 4) {
                    const int d2b = dy * dy + dx * dx;
                    const float wb = (d2b == 1) ? w1 : ((d2b == 2) ? w2 : w3);
                    float dv = v0 - B[j]; float t = dv * wb;
                    greg += t * rsqrtf(fmaf(dv, t, 1.0f));
                }
            }
        }

        float xn = v0 - ALPHA * (gd + BETA * greg);
        if (do_relu) xn = fmaxf(xn, 0.f);
        outcol[(size_t)z * HW] = xn;

        #pragma unroll
        for (int j = 0; j < 9; ++j) { A[j] = B[j]; B[j] = C[j]; }
    }
}

// ---------------------------------------------------------------------------
extern "C" void kernel_launch(void* const* d_in, const int* in_sizes, int n_in,
                              void* d_out, int out_size) {
    const float* slices = (const float*)d_in[1];
    const float* volume = (const float*)d_in[2];
    const float* psf    = (const float*)d_in[3];
    const int* stridep  = (const int*)d_in[4];

    int D = (int)lround(cbrt((double)out_size));   // 192
    int H = D, W = D;
    int n_slices = in_sizes[1] / (H * W);

    float *pE, *pA, *pB;
    cudaGetSymbolAddress((void**)&pE, d_E);
    cudaGetSymbolAddress((void**)&pA, d_A);
    cudaGetSymbolAddress((void**)&pB, d_B);

    init_p_kernel<<<1, 32>>>(psf);

    const bool spec = (D == 192 && H == 192 && W == 192 && n_slices == 96);

    dim3 blkE(32, 8, 1);
    dim3 grid_E2((W + 31) / 32, (H + 31) / 32, n_slices / 2);
    dim3 grid_E((W + 31) / 32, (H + 31) / 32, n_slices);
    dim3 blkU(32, 8, 1);
    dim3 grid_up((W + 31) / 32, (H + 7) / 8, (D + UPD_CHUNK - 1) / UPD_CHUNK);

    for (int it = 0; it < N_ITER; ++it) {
        const float* xin = (it == 0) ? volume : ((it & 1) ? pA : pB);
        float* xout = (it == N_ITER - 1) ? (float*)d_out
                                         : ((it & 1) ? pB : pA);
        int do_relu = (it == N_ITER - 1) ? 1 : 0;

        if (spec) {
            fused_E2_t<192, 192, 192, 96><<<grid_E2, blkE>>>(xin, slices, pE, stridep);
            update2_t<192, 192, 192, 96><<<grid_up, blkU>>>(xin, pE, xout, stridep, do_relu);
        } else {
            fused_E_gen<<<grid_E, blkE>>>(xin, slices, pE, stridep, D, H, W, n_slices);
            update_gen<<<grid_up, blkU>>>(xin, pE, xout, stridep, n_slices, D, H, W, do_relu);
        }
    }
}

// round 7
// speedup vs baseline: 2.1208x; 1.0184x over previous
#include <cuda_runtime.h>
#include <math.h>

#define N_ITER 10
#define UPD_CHUNK 24

static __device__ float d_p[5];                     // separable 1D psf
static __device__ float d_E[96 * 192 * 192];        // conv_xy(residual) planes
static __device__ float d_A[192 * 192 * 192];       // ping
static __device__ float d_B[192 * 192 * 192];       // pong

// ---------------------------------------------------------------------------
// packed f32x2 helpers (Blackwell)
// ---------------------------------------------------------------------------
__device__ __forceinline__ unsigned long long pk2(float lo, float hi) {
    unsigned long long r;
    asm("mov.b64 %0, {%1, %2};" : "=l"(r) : "f"(lo), "f"(hi));
    return r;
}
__device__ __forceinline__ void upk2(unsigned long long v, float& lo, float& hi) {
    asm("mov.b64 {%0, %1}, %2;" : "=f"(lo), "=f"(hi) : "l"(v));
}
__device__ __forceinline__ unsigned long long fma2_(unsigned long long a,
                                                    unsigned long long b,
                                                    unsigned long long c) {
    unsigned long long d;
    asm("fma.rn.f32x2 %0, %1, %2, %3;" : "=l"(d) : "l"(a), "l"(b), "l"(c));
    return d;
}
__device__ __forceinline__ unsigned long long mul2_(unsigned long long a,
                                                    unsigned long long b) {
    unsigned long long d;
    asm("mul.rn.f32x2 %0, %1, %2;" : "=l"(d) : "l"(a), "l"(b));
    return d;
}

// ---------------------------------------------------------------------------
__global__ void init_p_kernel(const float* __restrict__ psf) {
    int i = threadIdx.x;
    if (i < 5) {
        float s = 0.f;
        for (int j = 0; j < 25; ++j) s += psf[i * 25 + j];
        d_p[i] = s;
    }
}

// ===========================================================================
// Specialized kernels: compile-time D,H,W,NS (192,192,192,96); int offsets.
// ===========================================================================

// fused_E, 2 slices per block (shared 7-plane z window for stride 2).
template <int D, int H, int W, int NS>
__global__ __launch_bounds__(256, 5) void fused_E2_t(
    const float* __restrict__ x, const float* __restrict__ slices,
    float* __restrict__ E, const int* __restrict__ stridep) {
    constexpr int HW = H * W;
    __shared__ float bufZ[2][40][42];   // stage1 out; later overlaid by sF (36x37)
    __shared__ float bufA[2][40][36];   // stage2 out; later overlaid by sB (36x33)

    const int pr = blockIdx.z;
    const int stride = *stridep;
    const int iA = 2 * pr;
    const int ziA = iA * stride;
    const int x0 = blockIdx.x * 32, y0 = blockIdx.y * 32;
    const int tx = threadIdx.x, ty = threadIdx.y;

    const float p0 = d_p[0], p1 = d_p[1], p2 = d_p[2], p3 = d_p[3], p4 = d_p[4];

    const bool intXY = (x0 >= 4) && (x0 + 36 <= W) && (y0 >= 4) && (y0 + 36 <= H);

    // ---- stage 1: z-combine both slices ----
    if (stride == 2) {
        const int q0 = ziA - 2;                  // planes q0 .. q0+6
        const bool intZ = (q0 >= 0) && (ziA + 4 < D);
        if (intZ && intXY) {
            const float* base = x + q0 * HW + (y0 - 4) * W + (x0 - 4);
            #pragma unroll
            for (int k = 0; k < 5; ++k) {
                const int r = ty + 8 * k;
                const float* rowp = base + r * W;
                #pragma unroll
                for (int b = 0; b < 2; ++b) {
                    if (b == 1 && tx >= 8) break;
                    const int c = b * 32 + tx;
                    const float* col = rowp + c;
                    const float v0 = col[0],      v1 = col[HW],     v2 = col[2 * HW];
                    const float v3 = col[3 * HW], v4 = col[4 * HW], v5 = col[5 * HW];
                    const float v6 = col[6 * HW];
                    bufZ[0][r][c] = p0 * v0 + p1 * v1 + p2 * v2 + p3 * v3 + p4 * v4;
                    bufZ[1][r][c] = p0 * v2 + p1 * v3 + p2 * v4 + p3 * v5 + p4 * v6;
                }
            }
        } else {
            bool qok[7];
            #pragma unroll
            for (int j = 0; j < 7; ++j) qok[j] = (unsigned)(q0 + j) < (unsigned)D;
            #pragma unroll
            for (int k = 0; k < 5; ++k) {
                const int r = ty + 8 * k;
                const int gy = y0 - 4 + r;
                const bool okY = (unsigned)gy < (unsigned)H;
                #pragma unroll
                for (int b = 0; b < 2; ++b) {
                    if (b == 1 && tx >= 8) break;
                    const int c = b * 32 + tx;
                    const int gx = x0 - 4 + c;
                    const bool okXY = okY && (unsigned)gx < (unsigned)W;
                    const float* col = x + gy * W + gx;
                    float v[7];
                    #pragma unroll
                    for (int j = 0; j < 7; ++j)
                        v[j] = (okXY && qok[j]) ? col[(q0 + j) * HW] : 0.f;
                    bufZ[0][r][c] = p0 * v[0] + p1 * v[1] + p2 * v[2] + p3 * v[3] + p4 * v[4];
                    bufZ[1][r][c] = p0 * v[2] + p1 * v[3] + p2 * v[4] + p3 * v[5] + p4 * v[6];
                }
            }
        }
    } else {
        #pragma unroll
        for (int s = 0; s < 2; ++s) {
            const int zi = (iA + s) * stride;
            const int z0 = zi - 2;
            bool zok[5];
            #pragma unroll
            for (int j = 0; j < 5; ++j) zok[j] = (unsigned)(z0 + j) < (unsigned)D;
            #pragma unroll
            for (int k = 0; k < 5; ++k) {
                const int r = ty + 8 * k;
                const int gy = y0 - 4 + r;
                const bool okY = (unsigned)gy < (unsigned)H;
                #pragma unroll
                for (int b = 0; b < 2; ++b) {
                    if (b == 1 && tx >= 8) break;
                    const int c = b * 32 + tx;
                    const int gx = x0 - 4 + c;
                    const bool okXY = okY && (unsigned)gx < (unsigned)W;
                    const float* col = x + gy * W + gx;
                    float acc = 0.f;
                    if (okXY) {
                        if (zok[0]) acc = fmaf(p0, col[(z0 + 0) * HW], acc);
                        if (zok[1]) acc = fmaf(p1, col[(z0 + 1) * HW], acc);
                        if (zok[2]) acc = fmaf(p2, col[(z0 + 2) * HW], acc);
                        if (zok[3]) acc = fmaf(p3, col[(z0 + 3) * HW], acc);
                        if (zok[4]) acc = fmaf(p4, col[(z0 + 4) * HW], acc);
                    }
                    bufZ[s][r][c] = acc;
                }
            }
        }
    }
    __syncthreads();

    // ---- stage 2: x-conv into bufA (40 x 36) ----
    #pragma unroll
    for (int s = 0; s < 2; ++s) {
        #pragma unroll
        for (int k = 0; k < 5; ++k) {
            const int r = ty + 8 * k;
            bufA[s][r][tx] = p0 * bufZ[s][r][tx]     + p1 * bufZ[s][r][tx + 1]
                           + p2 * bufZ[s][r][tx + 2] + p3 * bufZ[s][r][tx + 3]
                           + p4 * bufZ[s][r][tx + 4];
            if (tx < 4) {
                const int c = 32 + tx;
                bufA[s][r][c] = p0 * bufZ[s][r][c]     + p1 * bufZ[s][r][c + 1]
                              + p2 * bufZ[s][r][c + 2] + p3 * bufZ[s][r][c + 3]
                              + p4 * bufZ[s][r][c + 4];
            }
        }
    }
    __syncthreads();

    // ---- stage 3: y-conv + subtract slice into sF (36 x 36, overlays bufZ) ----
    {
        float (*sF0)[37] = (float (*)[37]) &bufZ[0][0][0];
        float (*sF1)[37] = (float (*)[37]) &bufZ[1][0][0];
        #pragma unroll
        for (int s = 0; s < 2; ++s) {
            float (*sF)[37] = s ? sF1 : sF0;
            const float* sl = slices + (iA + s) * HW;
            if (intXY) {
                const float* sbase = sl + (y0 - 2) * W + (x0 - 2);
                #pragma unroll
                for (int k = 0; k < 5; ++k) {
                    const int r = (k < 4) ? (ty + 8 * k) : (32 + ty);
                    if (k == 4 && ty >= 4) break;
                    sF[r][tx] = p0 * bufA[s][r][tx]     + p1 * bufA[s][r + 1][tx]
                              + p2 * bufA[s][r + 2][tx] + p3 * bufA[s][r + 3][tx]
                              + p4 * bufA[s][r + 4][tx] - sbase[r * W + tx];
                    if (tx < 4) {
                        const int c = 32 + tx;
                        sF[r][c] = p0 * bufA[s][r][c]     + p1 * bufA[s][r + 1][c]
                                 + p2 * bufA[s][r + 2][c] + p3 * bufA[s][r + 3][c]
                                 + p4 * bufA[s][r + 4][c] - sbase[r * W + c];
                    }
                }
            } else {
                #pragma unroll
                for (int k = 0; k < 5; ++k) {
                    const int r = (k < 4) ? (ty + 8 * k) : (32 + ty);
                    if (k == 4 && ty >= 4) break;
                    const int gy = y0 - 2 + r;
                    const bool okY = (unsigned)gy < (unsigned)H;
                    #pragma unroll
                    for (int b = 0; b < 2; ++b) {
                        if (b == 1 && tx >= 4) break;
                        const int c = b * 32 + tx;
                        const int gx = x0 - 2 + c;
                        float v = 0.f;
                        if (okY && (unsigned)gx < (unsigned)W) {
                            v = p0 * bufA[s][r][c]     + p1 * bufA[s][r + 1][c]
                              + p2 * bufA[s][r + 2][c] + p3 * bufA[s][r + 3][c]
                              + p4 * bufA[s][r + 4][c] - sl[gy * W + gx];
                        }
                        sF[r][c] = v;
                    }
                }
            }
        }
    }
    __syncthreads();

    // ---- stage 4: x-conv into sB (36 x 32, overlays bufA) ----
    {
        float (*sF0)[37] = (float (*)[37]) &bufZ[0][0][0];
        float (*sF1)[37] = (float (*)[37]) &bufZ[1][0][0];
        float (*sB0)[33] = (float (*)[33]) &bufA[0][0][0];
        float (*sB1)[33] = (float (*)[33]) &bufA[1][0][0];
        #pragma unroll
        for (int s = 0; s < 2; ++s) {
            float (*sF)[37] = s ? sF1 : sF0;
            float (*sB)[33] = s ? sB1 : sB0;
            #pragma unroll
            for (int k = 0; k < 5; ++k) {
                const int r = (k < 4) ? (ty + 8 * k) : (32 + ty);
                if (k == 4 && ty >= 4) break;
                sB[r][tx] = p0 * sF[r][tx]     + p1 * sF[r][tx + 1] + p2 * sF[r][tx + 2]
                          + p3 * sF[r][tx + 3] + p4 * sF[r][tx + 4];
            }
        }
    }
    __syncthreads();

    // ---- stage 5: y-conv, store E (32 x 32 each) ----
    {
        float (*sB0)[33] = (float (*)[33]) &bufA[0][0][0];
        float (*sB1)[33] = (float (*)[33]) &bufA[1][0][0];
        #pragma unroll
        for (int s = 0; s < 2; ++s) {
            float (*sB)[33] = s ? sB1 : sB0;
            float* Ei = E + (iA + s) * HW + y0 * W + x0;
            #pragma unroll
            for (int k = 0; k < 4; ++k) {
                const int r = ty + 8 * k;
                Ei[r * W + tx] = p0 * sB[r][tx]     + p1 * sB[r + 1][tx]
                               + p2 * sB[r + 2][tx] + p3 * sB[r + 3][tx]
                               + p4 * sB[r + 4][tx];
            }
        }
    }
}

// ---------------------------------------------------------------------------
// update: 2 z per barrier, packed f32x2 regularizer for the voxel pair.
template <int D, int H, int W, int NS>
__global__ __launch_bounds__(256, 4) void update2_t(
    const float* __restrict__ xin, const float* __restrict__ E,
    float* __restrict__ xout, const int* __restrict__ stridep, int do_relu) {
    constexpr int HW = H * W;
    __shared__ float s[4][10][36];

    const int x0 = blockIdx.x * 32, y0 = blockIdx.y * 8;
    const int zb = blockIdx.z * UPD_CHUNK;        // even
    const int tx = threadIdx.x, ty = threadIdx.y;
    const int tid = ty * 32 + tx;
    const int y = y0 + ty, x = x0 + tx;
    const int stride = *stridep;

    const float p0 = d_p[0], p1 = d_p[1], p2 = d_p[2], p3 = d_p[3], p4 = d_p[4];

    const float w1 = (float)(1.0 / (1.0 * 0.1 * 0.1));
    const float w2 = (float)(1.0 / (2.0 * 0.1 * 0.1));
    const float w3 = (float)(1.0 / (3.0 * 0.1 * 0.1));

    // hoisted cooperative-load geometry (10*34 = 340 slots)
    const int ly0 = tid / 34, lx0 = tid % 34;
    const int gy0 = y0 - 1 + ly0, gx0 = x0 - 1 + lx0;
    const bool ok0 = (unsigned)gy0 < (unsigned)H && (unsigned)gx0 < (unsigned)W;
    const int off0 = ok0 ? (gy0 * W + gx0) : 0;

    const int i1 = tid + 256;
    const bool has1 = (i1 < 340);
    const int ly1 = has1 ? i1 / 34 : 0, lx1 = has1 ? i1 % 34 : 0;
    const int gy1 = y0 - 1 + ly1, gx1 = x0 - 1 + lx1;
    const bool ok1 = has1 && (unsigned)gy1 < (unsigned)H && (unsigned)gx1 < (unsigned)W;
    const int off1 = ok1 ? (gy1 * W + gx1) : 0;

    auto loadPlane = [&](int z, int sl) {
        const bool zok = (unsigned)z < (unsigned)D;
        const int zo = (zok ? z : 0) * HW;
        s[sl][ly0][lx0] = (zok && ok0) ? xin[zo + off0] : 0.f;
        if (has1) s[sl][ly1][lx1] = (zok && ok1) ? xin[zo + off1] : 0.f;
    };

    loadPlane(zb - 1, (zb - 1) & 3);
    loadPlane(zb, zb & 3);
    __syncthreads();

    float A[9], B[9];
    {
        const int sm = (zb - 1) & 3, s0 = zb & 3;
        #pragma unroll
        for (int dy = 0; dy < 3; ++dy)
            #pragma unroll
            for (int dx = 0; dx < 3; ++dx) {
                A[dy * 3 + dx] = s[sm][ty + dy][tx + dx];
                B[dy * 3 + dx] = s[s0][ty + dy][tx + dx];
            }
    }

    const bool interior_xy = (y > 0 && y < H - 1 && x > 0 && x < W - 1);
    const int eo = y * W + x;
    const float* Ecol = E + eo;
    float* outcol = xout + eo;
    const float ALPHA = 0.5f;
    const float BETA = (float)(0.02 * 0.1 * 0.1);

    auto regTerm = [&](const float* Av, const float* Bv, const float* Cv) -> float {
        float greg = 0.f;
        const float v0 = Bv[4];
        #pragma unroll
        for (int j = 0; j < 9; ++j) {
            const int dy = j / 3 - 1, dx = j % 3 - 1;
            const int d2a = dy * dy + dx * dx + 1;
            const float wa = (d2a == 1) ? w1 : ((d2a == 2) ? w2 : w3);
            { float dv = v0 - Av[j]; float t = dv * wa; greg += t * rsqrtf(fmaf(dv, t, 1.0f)); }
            { float dv = v0 - Cv[j]; float t = dv * wa; greg += t * rsqrtf(fmaf(dv, t, 1.0f)); }
            if (j != 4) {
                const int d2b = dy * dy + dx * dx;
                const float wb = (d2b == 1) ? w1 : ((d2b == 2) ? w2 : w3);
                float dv = v0 - Bv[j]; float t = dv * wb;
                greg += t * rsqrtf(fmaf(dv, t, 1.0f));
            }
        }
        return greg;
    };

    const int zend = (zb + UPD_CHUNK < D) ? (zb + UPD_CHUNK) : D;

    if (stride == 2) {
        int h = zb >> 1;
        float eA = (h >= 1) ? Ecol[(h - 1) * HW] : 0.f;
        float eB = (h < NS) ? Ecol[h * HW] : 0.f;
        float eC = (h + 1 < NS) ? Ecol[(h + 1) * HW] : 0.f;

        for (int z = zb; z < zend; z += 2, ++h) {
            const int s1 = (z + 1) & 3, s2 = (z + 2) & 3;
            loadPlane(z + 1, s1);
            loadPlane(z + 2, s2);
            __syncthreads();

            float C1[9], C2[9];
            #pragma unroll
            for (int dy = 0; dy < 3; ++dy)
                #pragma unroll
                for (int dx = 0; dx < 3; ++dx) {
                    C1[dy * 3 + dx] = s[s1][ty + dy][tx + dx];
                    C2[dy * 3 + dx] = s[s2][ty + dy][tx + dx];
                }

            // ---- packed f32x2 regularizer for voxel pair (z, z+1) ----
            float ge = 0.f, go = 0.f;
            if (interior_xy) {
                const unsigned long long v0p  = pk2(B[4], C1[4]);
                const unsigned long long one2 = pk2(1.0f, 1.0f);
                const unsigned long long m12  = pk2(-1.0f, -1.0f);
                unsigned long long acc = pk2(0.0f, 0.0f);

                #pragma unroll
                for (int j = 0; j < 9; ++j) {
                    const int dy = j / 3 - 1, dx = j % 3 - 1;
                    const int d2 = dy * dy + dx * dx;
                    const float wa = (d2 == 0) ? w1 : ((d2 == 1) ? w2 : w3); // dz=+-1
                    // dz = -1 : even uses A, odd uses B
                    {
                        const unsigned long long np = pk2(A[j], B[j]);
                        const unsigned long long dv = fma2_(np, m12, v0p);
                        const unsigned long long wp = pk2(wa, wa);
                        const unsigned long long t  = mul2_(dv, wp);
                        const unsigned long long ar = fma2_(dv, t, one2);
                        float a0, a1; upk2(ar, a0, a1);
                        const unsigned long long r = pk2(rsqrtf(a0), rsqrtf(a1));
                        acc = fma2_(t, r, acc);
                    }
                    // dz = +1 : even uses C1, odd uses C2
                    {
                        const unsigned long long np = pk2(C1[j], C2[j]);
                        const unsigned long long dv = fma2_(np, m12, v0p);
                        const unsigned long long wp = pk2(wa, wa);
                        const unsigned long long t  = mul2_(dv, wp);
                        const unsigned long long ar = fma2_(dv, t, one2);
                        float a0, a1; upk2(ar, a0, a1);
                        const unsigned long long r = pk2(rsqrtf(a0), rsqrtf(a1));
                        acc = fma2_(t, r, acc);
                    }
                    // dz = 0 : even uses B, odd uses C1
                    if (j != 4) {
                        const float wb = (d2 == 1) ? w1 : w2;
                        const unsigned long long np = pk2(B[j], C1[j]);
                        const unsigned long long dv = fma2_(np, m12, v0p);
                        const unsigned long long wp = pk2(wb, wb);
                        const unsigned long long t  = mul2_(dv, wp);
                        const unsigned long long ar = fma2_(dv, t, one2);
                        float a0, a1; upk2(ar, a0, a1);
                        const unsigned long long r = pk2(rsqrtf(a0), rsqrtf(a1));
                        acc = fma2_(t, r, acc);
                    }
                }
                upk2(acc, ge, go);
                if (z == 0) ge = 0.f;                  // dR zero-padded at z=0
                if (z + 1 == D - 1) go = 0.f;          // and at z=D-1
            }

            // ---- even z ----
            {
                float gd = fmaf(p0, eA, fmaf(p2, eB, p4 * eC));
                float xn = B[4] - ALPHA * (gd + BETA * ge);
                if (do_relu) xn = fmaxf(xn, 0.f);
                outcol[z * HW] = xn;
            }
            // ---- odd z+1 ----
            {
                float gd = fmaf(p1, eB, p3 * eC);
                float xn = C1[4] - ALPHA * (gd + BETA * go);
                if (do_relu) xn = fmaxf(xn, 0.f);
                outcol[(z + 1) * HW] = xn;
            }

            #pragma unroll
            for (int j = 0; j < 9; ++j) { A[j] = C1[j]; B[j] = C2[j]; }
            eA = eB; eB = eC;
            eC = (h + 2 < NS) ? Ecol[(h + 2) * HW] : 0.f;
        }
    } else {
        const float pz[5] = {p0, p1, p2, p3, p4};
        for (int z = zb; z < zend; ++z) {
            const int sl = (z + 1) & 3;
            loadPlane(z + 1, sl);
            __syncthreads();
            float C[9];
            #pragma unroll
            for (int dy = 0; dy < 3; ++dy)
                #pragma unroll
                for (int dx = 0; dx < 3; ++dx)
                    C[dy * 3 + dx] = s[sl][ty + dy][tx + dx];

            float gd = 0.f;
            #pragma unroll
            for (int dz = 0; dz < 5; ++dz) {
                int zz = z + dz - 2;
                if ((unsigned)zz < (unsigned)D && (zz % stride) == 0) {
                    int pi = zz / stride;
                    if (pi < NS) gd = fmaf(pz[dz], Ecol[pi * HW], gd);
                }
            }
            float greg = 0.f;
            if (interior_xy && z > 0 && z < D - 1) greg = regTerm(A, B, C);
            float xn = B[4] - ALPHA * (gd + BETA * greg);
            if (do_relu) xn = fmaxf(xn, 0.f);
            outcol[z * HW] = xn;
            #pragma unroll
            for (int j = 0; j < 9; ++j) { A[j] = B[j]; B[j] = C[j]; }
        }
    }
}

// ===========================================================================
// Generic fallback kernels (runtime dims) — validated in R4/R5.
// ===========================================================================

__global__ __launch_bounds__(256) void fused_E_gen(
    const float* __restrict__ x, const float* __restrict__ slices,
    float* __restrict__ E, const int* __restrict__ stridep,
    int D, int H, int W, int n_slices) {
    __shared__ float sZ[40][44];
    __shared__ float sA[40][36];
    __shared__ float sF[36][36];
    __shared__ float sB[36][33];

    const int i = blockIdx.z;
    const int zi = i * (*stridep);
    const int x0 = blockIdx.x * 32, y0 = blockIdx.y * 32;
    const int tx = threadIdx.x, ty = threadIdx.y;
    const size_t HW = (size_t)H * W;

    const float p0 = d_p[0], p1 = d_p[1], p2 = d_p[2], p3 = d_p[3], p4 = d_p[4];

    {
        const int z0 = zi - 2;
        const bool zok0 = (z0 >= 0), zok1 = (z0 + 1 >= 0);
        const bool zok2 = (z0 + 2 >= 0) && (z0 + 2 < D);
        const bool zok3 = (z0 + 3 < D), zok4 = (z0 + 4 < D);
        #pragma unroll
        for (int k = 0; k < 5; ++k) {
            const int r = ty + 8 * k;
            const int gy = y0 - 4 + r;
            const bool okY = (unsigned)gy < (unsigned)H;
            #pragma unroll
            for (int b = 0; b < 2; ++b) {
                const int c = b * 32 + tx;
                if (b == 1 && tx >= 8) break;
                const int gx = x0 - 4 + c;
                float acc = 0.f;
                if (okY && (unsigned)gx < (unsigned)W) {
                    const float* col = x + (size_t)gy * W + gx + (size_t)z0 * HW;
                    if (zok0) acc = fmaf(p0, col[0], acc);
                    if (zok1) acc = fmaf(p1, col[HW], acc);
                    if (zok2) acc = fmaf(p2, col[2 * HW], acc);
                    if (zok3) acc = fmaf(p3, col[3 * HW], acc);
                    if (zok4) acc = fmaf(p4, col[4 * HW], acc);
                }
                sZ[r][c] = acc;
            }
        }
    }
    __syncthreads();

    #pragma unroll
    for (int k = 0; k < 5; ++k) {
        const int r = ty + 8 * k;
        sA[r][tx] = p0 * sZ[r][tx]     + p1 * sZ[r][tx + 1] + p2 * sZ[r][tx + 2]
                  + p3 * sZ[r][tx + 3] + p4 * sZ[r][tx + 4];
        if (tx < 4) {
            const int c = 32 + tx;
            sA[r][c] = p0 * sZ[r][c]     + p1 * sZ[r][c + 1] + p2 * sZ[r][c + 2]
                     + p3 * sZ[r][c + 3] + p4 * sZ[r][c + 4];
        }
    }
    __syncthreads();

    {
        const float* sl = slices + (size_t)i * HW;
        #pragma unroll
        for (int k = 0; k < 5; ++k) {
            const int r = (k < 4) ? (ty + 8 * k) : (32 + ty);
            if (k == 4 && ty >= 4) break;
            const int gy = y0 - 2 + r;
            const bool okY = (unsigned)gy < (unsigned)H;
            #pragma unroll
            for (int b = 0; b < 2; ++b) {
                const int c = b * 32 + tx;
                if (b == 1 && tx >= 4) break;
                const int gx = x0 - 2 + c;
                float v = 0.f;
                if (okY && (unsigned)gx < (unsigned)W) {
                    v = p0 * sA[r][c]     + p1 * sA[r + 1][c] + p2 * sA[r + 2][c]
                      + p3 * sA[r + 3][c] + p4 * sA[r + 4][c]
                      - sl[(size_t)gy * W + gx];
                }
                sF[r][c] = v;
            }
        }
    }
    __syncthreads();

    #pragma unroll
    for (int k = 0; k < 5; ++k) {
        const int r = (k < 4) ? (ty + 8 * k) : (32 + ty);
        if (k == 4 && ty >= 4) break;
        sB[r][tx] = p0 * sF[r][tx]     + p1 * sF[r][tx + 1] + p2 * sF[r][tx + 2]
                  + p3 * sF[r][tx + 3] + p4 * sF[r][tx + 4];
    }
    __syncthreads();

    {
        float* Ei = E + (size_t)i * HW;
        #pragma unroll
        for (int k = 0; k < 4; ++k) {
            const int r = ty + 8 * k;
            const int gy = y0 + r, gx = x0 + tx;
            if (gy < H && gx < W) {
                Ei[(size_t)gy * W + gx] =
                      p0 * sB[r][tx]     + p1 * sB[r + 1][tx] + p2 * sB[r + 2][tx]
                    + p3 * sB[r + 3][tx] + p4 * sB[r + 4][tx];
            }
        }
    }
}

__global__ __launch_bounds__(256, 4) void update_gen(
    const float* __restrict__ xin, const float* __restrict__ E,
    float* __restrict__ xout, const int* __restrict__ stridep,
    int n_slices, int D, int H, int W, int do_relu) {
    __shared__ float s[3][10][36];

    const int x0 = blockIdx.x * 32, y0 = blockIdx.y * 8;
    const int zb = blockIdx.z * UPD_CHUNK;
    const int tx = threadIdx.x, ty = threadIdx.y;
    const int tid = ty * 32 + tx;
    const size_t HW = (size_t)H * W;
    const int y = y0 + ty, x = x0 + tx;
    const int stride = *stridep;

    const float p0 = d_p[0], p1 = d_p[1], p2 = d_p[2], p3 = d_p[3], p4 = d_p[4];
    const float pz[5] = {p0, p1, p2, p3, p4};
    const float w1 = (float)(1.0 / (1.0 * 0.1 * 0.1));
    const float w2 = (float)(1.0 / (2.0 * 0.1 * 0.1));
    const float w3 = (float)(1.0 / (3.0 * 0.1 * 0.1));

    const int ly0 = tid / 34, lx0 = tid % 34;
    const int gy0 = y0 - 1 + ly0, gx0 = x0 - 1 + lx0;
    const bool ok0 = (unsigned)gy0 < (unsigned)H && (unsigned)gx0 < (unsigned)W;
    const size_t off0 = ok0 ? ((size_t)gy0 * W + gx0) : 0;
    const int i1 = tid + 256;
    const bool has1 = (i1 < 340);
    const int ly1 = has1 ? i1 / 34 : 0, lx1 = has1 ? i1 % 34 : 0;
    const int gy1 = y0 - 1 + ly1, gx1 = x0 - 1 + lx1;
    const bool ok1 = has1 && (unsigned)gy1 < (unsigned)H && (unsigned)gx1 < (unsigned)W;
    const size_t off1 = ok1 ? ((size_t)gy1 * W + gx1) : 0;

    auto loadPlane = [&](int z, int sl) {
        const bool zok = (unsigned)z < (unsigned)D;
        const size_t zo = (size_t)(zok ? z : 0) * HW;
        s[sl][ly0][lx0] = (zok && ok0) ? xin[zo + off0] : 0.f;
        if (has1) s[sl][ly1][lx1] = (zok && ok1) ? xin[zo + off1] : 0.f;
    };

    const int sl_m1 = ((zb - 1) % 3 + 3) % 3;
    const int sl_0  = zb % 3;
    loadPlane(zb - 1, sl_m1);
    loadPlane(zb, sl_0);
    __syncthreads();

    float A[9], B[9];
    #pragma unroll
    for (int dy = 0; dy < 3; ++dy)
        #pragma unroll
        for (int dx = 0; dx < 3; ++dx) {
            A[dy * 3 + dx] = s[sl_m1][ty + dy][tx + dx];
            B[dy * 3 + dx] = s[sl_0][ty + dy][tx + dx];
        }

    const bool interior_xy = (y > 0 && y < H - 1 && x > 0 && x < W - 1);
    const size_t eo = (size_t)y * W + x;
    const float* Ecol = E + eo;
    float* outcol = xout + eo;
    const float ALPHA = 0.5f;
    const float BETA = (float)(0.02 * 0.1 * 0.1);

    int zend = zb + UPD_CHUNK;
    if (zend > D) zend = D;

    for (int z = zb; z < zend; ++z) {
        const int sl = (z + 1) % 3;
        loadPlane(z + 1, sl);
        __syncthreads();

        float C[9];
        #pragma unroll
        for (int dy = 0; dy < 3; ++dy)
            #pragma unroll
            for (int dx = 0; dx < 3; ++dx)
                C[dy * 3 + dx] = s[sl][ty + dy][tx + dx];

        const float v0 = B[4];
        float gd = 0.f;
        #pragma unroll
        for (int dz = 0; dz < 5; ++dz) {
            int zz = z + dz - 2;
            if ((unsigned)zz < (unsigned)D && (zz % stride) == 0) {
                int pi = zz / stride;
                if (pi < n_slices) gd = fmaf(pz[dz], Ecol[(size_t)pi * HW], gd);
            }
        }

        float greg = 0.f;
        if (interior_xy && z > 0 && z < D - 1) {
            #pragma unroll
            for (int j = 0; j < 9; ++j) {
                const int dy = j / 3 - 1, dx = j % 3 - 1;
                const int d2a = dy * dy + dx * dx + 1;
                const float wa = (d2a == 1) ? w1 : ((d2a == 2) ? w2 : w3);
                { float dv = v0 - A[j]; float t = dv * wa; greg += t * rsqrtf(fmaf(dv, t, 1.0f)); }
                { float dv = v0 - C[j]; float t = dv * wa; greg += t * rsqrtf(fmaf(dv, t, 1.0f)); }
                if (j != 4) {
                    const int d2b = dy * dy + dx * dx;
                    const float wb = (d2b == 1) ? w1 : ((d2b == 2) ? w2 : w3);
                    float dv = v0 - B[j]; float t = dv * wb;
                    greg += t * rsqrtf(fmaf(dv, t, 1.0f));
                }
            }
        }

        float xn = v0 - ALPHA * (gd + BETA * greg);
        if (do_relu) xn = fmaxf(xn, 0.f);
        outcol[(size_t)z * HW] = xn;

        #pragma unroll
        for (int j = 0; j < 9; ++j) { A[j] = B[j]; B[j] = C[j]; }
    }
}

// ---------------------------------------------------------------------------
extern "C" void kernel_launch(void* const* d_in, const int* in_sizes, int n_in,
                              void* d_out, int out_size) {
    const float* slices = (const float*)d_in[1];
    const float* volume = (const float*)d_in[2];
    const float* psf    = (const float*)d_in[3];
    const int* stridep  = (const int*)d_in[4];

    int D = (int)lround(cbrt((double)out_size));   // 192
    int H = D, W = D;
    int n_slices = in_sizes[1] / (H * W);

    float *pE, *pA, *pB;
    cudaGetSymbolAddress((void**)&pE, d_E);
    cudaGetSymbolAddress((void**)&pA, d_A);
    cudaGetSymbolAddress((void**)&pB, d_B);

    init_p_kernel<<<1, 32>>>(psf);

    const bool spec = (D == 192 && H == 192 && W == 192 && n_slices == 96);

    dim3 blkE(32, 8, 1);
    dim3 grid_E2((W + 31) / 32, (H + 31) / 32, n_slices / 2);
    dim3 grid_E((W + 31) / 32, (H + 31) / 32, n_slices);
    dim3 blkU(32, 8, 1);
    dim3 grid_up((W + 31) / 32, (H + 7) / 8, (D + UPD_CHUNK - 1) / UPD_CHUNK);

    for (int it = 0; it < N_ITER; ++it) {
        const float* xin = (it == 0) ? volume : ((it & 1) ? pA : pB);
        float* xout = (it == N_ITER - 1) ? (float*)d_out
                                         : ((it & 1) ? pB : pA);
        int do_relu = (it == N_ITER - 1) ? 1 : 0;

        if (spec) {
            fused_E2_t<192, 192, 192, 96><<<grid_E2, blkE>>>(xin, slices, pE, stridep);
            update2_t<192, 192, 192, 96><<<grid_up, blkU>>>(xin, pE, xout, stridep, do_relu);
        } else {
            fused_E_gen<<<grid_E, blkE>>>(xin, slices, pE, stridep, D, H, W, n_slices);
            update_gen<<<grid_up, blkU>>>(xin, pE, xout, stridep, n_slices, D, H, W, do_relu);
        }
    }
}